// round 1
// baseline (speedup 1.0000x reference)
#include <cuda_runtime.h>
#include <math.h>

// Problem constants
#define BN 4
#define SN 2048
#define HN 1024

// Scratch (allocation-free rule: __device__ globals)
__device__ float g_Q[(size_t)BN * SN * HN];
__device__ float g_Kp[(size_t)BN * SN * HN];
__device__ float g_Vp[(size_t)BN * SN * HN];
__device__ float g_P[(size_t)BN * SN * SN];

// ---------------------------------------------------------------------------
// NT GEMM: C[M,N] = scale * (A[M,K] @ B[N,K]^T) + bias[N]
// 128x128 block tile, 8x8 per thread, BK=8, 256 threads.
// Requires M%128==0, N%128==0, K%8==0 (true for all call sites).
// ---------------------------------------------------------------------------
__global__ __launch_bounds__(256) void gemm_nt(
    const float* __restrict__ A, const float* __restrict__ Bm,
    const float* __restrict__ bias, float* __restrict__ C,
    int M, int N, int K, float scale,
    size_t sA, size_t sB, size_t sC)
{
    A  += (size_t)blockIdx.z * sA;
    Bm += (size_t)blockIdx.z * sB;
    C  += (size_t)blockIdx.z * sC;

    __shared__ float As[8][128];
    __shared__ float Bs[8][128];

    const int tid = threadIdx.x;
    const int tr  = tid >> 4;   // 0..15
    const int tc  = tid & 15;   // 0..15
    const int rowBase = blockIdx.y * 128;
    const int colBase = blockIdx.x * 128;

    // Loader mapping: 128 rows x 8 k, one float4 per thread
    const int lr = tid >> 1;        // 0..127
    const int lc = (tid & 1) * 4;   // 0 or 4

    const float* Aptr = A  + (size_t)(rowBase + lr) * K + lc;
    const float* Bptr = Bm + (size_t)(colBase + lr) * K + lc;

    float acc[8][8];
    #pragma unroll
    for (int i = 0; i < 8; i++)
        #pragma unroll
        for (int j = 0; j < 8; j++) acc[i][j] = 0.0f;

    for (int kt = 0; kt < K; kt += 8) {
        float4 a4 = *(const float4*)(Aptr + kt);
        float4 b4 = *(const float4*)(Bptr + kt);
        As[lc + 0][lr] = a4.x; As[lc + 1][lr] = a4.y;
        As[lc + 2][lr] = a4.z; As[lc + 3][lr] = a4.w;
        Bs[lc + 0][lr] = b4.x; Bs[lc + 1][lr] = b4.y;
        Bs[lc + 2][lr] = b4.z; Bs[lc + 3][lr] = b4.w;
        __syncthreads();

        #pragma unroll
        for (int k = 0; k < 8; k++) {
            float ar[8], br[8];
            #pragma unroll
            for (int i = 0; i < 8; i++) ar[i] = As[k][tr * 8 + i];
            #pragma unroll
            for (int j = 0; j < 8; j++) br[j] = Bs[k][tc * 8 + j];
            #pragma unroll
            for (int i = 0; i < 8; i++)
                #pragma unroll
                for (int j = 0; j < 8; j++)
                    acc[i][j] = fmaf(ar[i], br[j], acc[i][j]);
        }
        __syncthreads();
    }

    #pragma unroll
    for (int i = 0; i < 8; i++) {
        const size_t row = (size_t)(rowBase + tr * 8 + i);
        float* Crow = C + row * N + colBase + tc * 8;
        #pragma unroll
        for (int j = 0; j < 8; j += 4) {
            float4 v;
            float b0 = bias ? bias[colBase + tc * 8 + j + 0] : 0.0f;
            float b1 = bias ? bias[colBase + tc * 8 + j + 1] : 0.0f;
            float b2 = bias ? bias[colBase + tc * 8 + j + 2] : 0.0f;
            float b3 = bias ? bias[colBase + tc * 8 + j + 3] : 0.0f;
            v.x = acc[i][j + 0] * scale + b0;
            v.y = acc[i][j + 1] * scale + b1;
            v.z = acc[i][j + 2] * scale + b2;
            v.w = acc[i][j + 3] * scale + b3;
            *(float4*)(Crow + j) = v;
        }
    }
}

// ---------------------------------------------------------------------------
// NN GEMM: C[M,N] = A[M,K] @ B[K,N]   (B row-major, N contiguous)
// Same tiling as gemm_nt.
// ---------------------------------------------------------------------------
__global__ __launch_bounds__(256) void gemm_nn(
    const float* __restrict__ A, const float* __restrict__ Bm,
    float* __restrict__ C,
    int M, int N, int K,
    size_t sA, size_t sB, size_t sC)
{
    A  += (size_t)blockIdx.z * sA;
    Bm += (size_t)blockIdx.z * sB;
    C  += (size_t)blockIdx.z * sC;

    __shared__ float As[8][128];
    __shared__ float Bs[8][128];

    const int tid = threadIdx.x;
    const int tr  = tid >> 4;
    const int tc  = tid & 15;
    const int rowBase = blockIdx.y * 128;
    const int colBase = blockIdx.x * 128;

    // A loader: 128 rows x 8 k (transposed store)
    const int lr = tid >> 1;
    const int lc = (tid & 1) * 4;
    // B loader: 8 k-rows x 128 n
    const int br_row = tid >> 5;        // 0..7
    const int br_col = (tid & 31) * 4;  // 0..124

    const float* Aptr = A + (size_t)(rowBase + lr) * K + lc;

    float acc[8][8];
    #pragma unroll
    for (int i = 0; i < 8; i++)
        #pragma unroll
        for (int j = 0; j < 8; j++) acc[i][j] = 0.0f;

    for (int kt = 0; kt < K; kt += 8) {
        float4 a4 = *(const float4*)(Aptr + kt);
        float4 b4 = *(const float4*)(Bm + (size_t)(kt + br_row) * N + colBase + br_col);
        As[lc + 0][lr] = a4.x; As[lc + 1][lr] = a4.y;
        As[lc + 2][lr] = a4.z; As[lc + 3][lr] = a4.w;
        *(float4*)&Bs[br_row][br_col] = b4;
        __syncthreads();

        #pragma unroll
        for (int k = 0; k < 8; k++) {
            float ar[8], br[8];
            #pragma unroll
            for (int i = 0; i < 8; i++) ar[i] = As[k][tr * 8 + i];
            #pragma unroll
            for (int j = 0; j < 8; j++) br[j] = Bs[k][tc * 8 + j];
            #pragma unroll
            for (int i = 0; i < 8; i++)
                #pragma unroll
                for (int j = 0; j < 8; j++)
                    acc[i][j] = fmaf(ar[i], br[j], acc[i][j]);
        }
        __syncthreads();
    }

    #pragma unroll
    for (int i = 0; i < 8; i++) {
        const size_t row = (size_t)(rowBase + tr * 8 + i);
        float* Crow = C + row * N + colBase + tc * 8;
        #pragma unroll
        for (int j = 0; j < 8; j += 4) {
            float4 v;
            v.x = acc[i][j + 0]; v.y = acc[i][j + 1];
            v.z = acc[i][j + 2]; v.w = acc[i][j + 3];
            *(float4*)(Crow + j) = v;
        }
    }
}

// ---------------------------------------------------------------------------
// Row softmax over n=2048 columns. One block (256 threads) per row.
// ---------------------------------------------------------------------------
__global__ __launch_bounds__(256) void softmax_rows(float* __restrict__ P, int n)
{
    float* row = P + (size_t)blockIdx.x * n;
    const int tid  = threadIdx.x;
    const int lane = tid & 31;
    const int wid  = tid >> 5;
    __shared__ float red[8];

    float v[8];
    float m = -INFINITY;
    #pragma unroll
    for (int i = 0; i < 8; i++) {
        v[i] = row[tid + i * 256];
        m = fmaxf(m, v[i]);
    }
    #pragma unroll
    for (int o = 16; o > 0; o >>= 1)
        m = fmaxf(m, __shfl_xor_sync(0xFFFFFFFFu, m, o));
    if (lane == 0) red[wid] = m;
    __syncthreads();
    float mb = red[0];
    #pragma unroll
    for (int w = 1; w < 8; w++) mb = fmaxf(mb, red[w]);
    __syncthreads();

    float s = 0.0f;
    #pragma unroll
    for (int i = 0; i < 8; i++) {
        v[i] = __expf(v[i] - mb);
        s += v[i];
    }
    #pragma unroll
    for (int o = 16; o > 0; o >>= 1)
        s += __shfl_xor_sync(0xFFFFFFFFu, s, o);
    if (lane == 0) red[wid] = s;
    __syncthreads();
    float sb = 0.0f;
    #pragma unroll
    for (int w = 0; w < 8; w++) sb += red[w];
    const float r = 1.0f / sb;

    #pragma unroll
    for (int i = 0; i < 8; i++)
        row[tid + i * 256] = v[i] * r;
}

// ---------------------------------------------------------------------------
// Launch
// ---------------------------------------------------------------------------
extern "C" void kernel_launch(void* const* d_in, const int* in_sizes, int n_in,
                              void* d_out, int out_size)
{
    (void)in_sizes; (void)n_in; (void)out_size;
    const float* x  = (const float*)d_in[0];
    const float* Wq = (const float*)d_in[1];
    const float* bq = (const float*)d_in[2];
    const float* Wk = (const float*)d_in[3];
    const float* bk = (const float*)d_in[4];
    const float* Wv = (const float*)d_in[5];
    const float* bv = (const float*)d_in[6];
    float* out = (float*)d_out;

    float *Q, *K, *V, *P;
    cudaGetSymbolAddress((void**)&Q, g_Q);
    cudaGetSymbolAddress((void**)&K, g_Kp);
    cudaGetSymbolAddress((void**)&V, g_Vp);
    cudaGetSymbolAddress((void**)&P, g_P);

    const int M   = BN * SN;              // 8192
    const size_t strQKV = (size_t)SN * HN;
    const size_t strP   = (size_t)SN * SN;
    const float  scl    = 0.03125f;       // 1/sqrt(1024)

    // 1) Q/K/V projections: [8192,1024] = x @ W^T + b
    {
        dim3 grid(HN / 128, M / 128, 1);
        gemm_nt<<<grid, 256>>>(x, Wq, bq, Q, M, HN, HN, 1.0f, 0, 0, 0);
        gemm_nt<<<grid, 256>>>(x, Wk, bk, K, M, HN, HN, 1.0f, 0, 0, 0);
        gemm_nt<<<grid, 256>>>(x, Wv, bv, V, M, HN, HN, 1.0f, 0, 0, 0);
    }

    // 2) scores = Q @ K^T / 32, per batch
    {
        dim3 grid(SN / 128, SN / 128, BN);
        gemm_nt<<<grid, 256>>>(Q, K, nullptr, P, SN, SN, HN, scl,
                               strQKV, strQKV, strP);
    }

    // 3) softmax over rows
    softmax_rows<<<BN * SN, 256>>>(P, SN);

    // 4) out = P @ V, per batch
    {
        dim3 grid(HN / 128, SN / 128, BN);
        gemm_nn<<<grid, 256>>>(P, V, out, SN, HN, SN,
                               strP, strQKV, strQKV);
    }
}

// round 3
// speedup vs baseline: 2.7657x; 2.7657x over previous
#include <cuda_runtime.h>
#include <cuda_bf16.h>
#include <math.h>
#include <stdint.h>

#define BN 4
#define SN 2048
#define HN 1024
#define MTOT (BN * SN)

// ---------------------------------------------------------------------------
// Scratch (__device__ globals; allocation-free rule)
// ---------------------------------------------------------------------------
__device__ __nv_bfloat16 g_xh[(size_t)MTOT * HN], g_xl[(size_t)MTOT * HN];
__device__ __nv_bfloat16 g_Wqh[(size_t)HN * HN], g_Wql[(size_t)HN * HN];
__device__ __nv_bfloat16 g_Wkh[(size_t)HN * HN], g_Wkl[(size_t)HN * HN];
__device__ __nv_bfloat16 g_Wvh[(size_t)HN * HN], g_Wvl[(size_t)HN * HN];
__device__ __nv_bfloat16 g_Qh[(size_t)MTOT * HN], g_Ql[(size_t)MTOT * HN];
__device__ __nv_bfloat16 g_KhA[(size_t)MTOT * HN], g_KlA[(size_t)MTOT * HN];
__device__ __nv_bfloat16 g_Vth[(size_t)BN * HN * SN], g_Vtl[(size_t)BN * HN * SN];
__device__ float         g_P[(size_t)BN * SN * SN];
__device__ __nv_bfloat16 g_Ph[(size_t)BN * SN * SN], g_Pl[(size_t)BN * SN * SN];

// ---------------------------------------------------------------------------
// Helpers (compute_103-safe: ldmatrix + mma.sync + cp.async only)
// ---------------------------------------------------------------------------
__device__ __forceinline__ uint32_t smem_u32(const void* p) {
    uint32_t a;
    asm("{ .reg .u64 t; cvta.to.shared.u64 t, %1; cvt.u32.u64 %0, t; }" : "=r"(a) : "l"(p));
    return a;
}
__device__ __forceinline__ void ldsm_x4(uint32_t* r, uint32_t a) {
    asm volatile("ldmatrix.sync.aligned.m8n8.x4.shared.b16 {%0,%1,%2,%3}, [%4];"
                 : "=r"(r[0]), "=r"(r[1]), "=r"(r[2]), "=r"(r[3]) : "r"(a));
}
__device__ __forceinline__ void mma_bf16(float* c, const uint32_t* a,
                                         uint32_t b0, uint32_t b1) {
    asm volatile("mma.sync.aligned.m16n8k16.row.col.f32.bf16.bf16.f32 "
                 "{%0,%1,%2,%3}, {%4,%5,%6,%7}, {%8,%9}, {%0,%1,%2,%3};"
                 : "+f"(c[0]), "+f"(c[1]), "+f"(c[2]), "+f"(c[3])
                 : "r"(a[0]), "r"(a[1]), "r"(a[2]), "r"(a[3]), "r"(b0), "r"(b1));
}
#define CP_COMMIT() asm volatile("cp.async.commit_group;" ::: "memory")
#define CP_WAIT1()  asm volatile("cp.async.wait_group 1;" ::: "memory")
#define CP_WAIT0()  asm volatile("cp.async.wait_group 0;" ::: "memory")

// ---------------------------------------------------------------------------
// NT GEMM via mma.sync bf16, 3-pass hi/lo split:
//   C[M,N] = scale * sum_k (Ah·Bh + Ah·Bl + Al·Bh) + bias
// Tile 128x128, BK=64 (128B rows, SW128 xor swizzle), 256 threads,
// warp grid 4(m) x 2(n), warp tile 32x64. 2-stage cp.async pipeline.
// biasMode: 0 none, 1 bias[col], 2 bias[row].  outMode: 0 fp32, 1 bf16 hi/lo.
// ---------------------------------------------------------------------------
#define TILE_BYTES  16384
#define STAGE_BYTES (4 * TILE_BYTES)

__global__ __launch_bounds__(256, 1)
void mma_gemm(const __nv_bfloat16* __restrict__ Ah, const __nv_bfloat16* __restrict__ Al,
              const __nv_bfloat16* __restrict__ Bh, const __nv_bfloat16* __restrict__ Bl,
              const float* __restrict__ bias, int biasMode, float scale,
              float* __restrict__ Cf, __nv_bfloat16* __restrict__ Ch,
              __nv_bfloat16* __restrict__ Cl, int outMode, int K, int ldc,
              size_t szA, size_t szB, size_t szC)
{
    extern __shared__ char smem[];
    const uint32_t sb = smem_u32(smem);
    const int tid = threadIdx.x, lane = tid & 31, wid = tid >> 5;
    const int wm = wid & 3, wn = wid >> 2;

    Ah += (size_t)blockIdx.z * szA;  Al += (size_t)blockIdx.z * szA;
    Bh += (size_t)blockIdx.z * szB;  Bl += (size_t)blockIdx.z * szB;
    if (outMode == 0) Cf += (size_t)blockIdx.z * szC;
    else { Ch += (size_t)blockIdx.z * szC; Cl += (size_t)blockIdx.z * szC; }

    const int rowBase = blockIdx.y * 128;
    const int colBase = blockIdx.x * 128;

    const __nv_bfloat16* tAh = Ah + (size_t)rowBase * K;
    const __nv_bfloat16* tAl = Al + (size_t)rowBase * K;
    const __nv_bfloat16* tBh = Bh + (size_t)colBase * K;
    const __nv_bfloat16* tBl = Bl + (size_t)colBase * K;

    const int NK = K >> 6;

    // ---- stage loader: 16B cp.async, SW128 swizzle, 4 iters per 16KB tile
    auto load_tile = [&](uint32_t dst, const __nv_bfloat16* g) {
        #pragma unroll
        for (int i = 0; i < 4; i++) {
            int idx = i * 256 + tid;
            int row = idx >> 3;
            int kb  = idx & 7;
            uint32_t off = row * 128 + kb * 16;
            uint32_t sw  = off ^ ((off >> 3) & 0x70);
            const void* src = (const void*)(g + (size_t)row * K + kb * 8);
            asm volatile("cp.async.cg.shared.global [%0], [%1], 16;"
                         :: "r"(dst + sw), "l"(src));
        }
    };
    auto load_stage = [&](int buf, int c) {
        uint32_t st = sb + buf * STAGE_BYTES;
        size_t ko = (size_t)c * 64;
        load_tile(st,                  tAh + ko);
        load_tile(st + TILE_BYTES,     tAl + ko);
        load_tile(st + 2 * TILE_BYTES, tBh + ko);
        load_tile(st + 3 * TILE_BYTES, tBl + ko);
        CP_COMMIT();
    };

    float acc[2][8][4];
    #pragma unroll
    for (int i = 0; i < 2; i++)
        #pragma unroll
        for (int j = 0; j < 8; j++)
            #pragma unroll
            for (int q = 0; q < 4; q++) acc[i][j][q] = 0.0f;

    // per-lane ldmatrix addressing: lane group -> (row within 16, k-atom half)
    const int lm = lane & 15;
    const int lk = lane >> 4;
    // A rows for 2 m16 tiles; B rows for 4 n16 groups
    int rA[2], rB[4];
    #pragma unroll
    for (int i = 0; i < 2; i++) rA[i] = wm * 32 + i * 16 + lm;
    #pragma unroll
    for (int g = 0; g < 4; g++) rB[g] = wn * 64 + g * 16 + lm;

    load_stage(0, 0);

    for (int c = 0; c < NK; c++) {
        if (c + 1 < NK) { load_stage((c + 1) & 1, c + 1); CP_WAIT1(); }
        else           { CP_WAIT0(); }
        __syncthreads();

        const uint32_t stage = sb + (c & 1) * STAGE_BYTES;
        #pragma unroll
        for (int pass = 0; pass < 3; pass++) {
            const uint32_t tA = stage + (pass == 2 ? TILE_BYTES : 0);
            const uint32_t tB = stage + 2 * TILE_BYTES + (pass == 1 ? TILE_BYTES : 0);
            #pragma unroll
            for (int ks = 0; ks < 4; ks++) {
                uint32_t a0[4], a1[4];
                {
                    int atom = ks * 2 + lk;
                    ldsm_x4(a0, tA + rA[0] * 128 + (((atom) ^ (rA[0] & 7)) << 4));
                    ldsm_x4(a1, tA + rA[1] * 128 + (((atom) ^ (rA[1] & 7)) << 4));
                }
                uint32_t bf[4][4];
                #pragma unroll
                for (int g = 0; g < 4; g++) {
                    int atom = ks * 2 + lk;
                    ldsm_x4(bf[g], tB + rB[g] * 128 + (((atom) ^ (rB[g] & 7)) << 4));
                }
                #pragma unroll
                for (int g = 0; g < 4; g++) {
                    mma_bf16(acc[0][2 * g + 0], a0, bf[g][0], bf[g][2]);
                    mma_bf16(acc[0][2 * g + 1], a0, bf[g][1], bf[g][3]);
                    mma_bf16(acc[1][2 * g + 0], a1, bf[g][0], bf[g][2]);
                    mma_bf16(acc[1][2 * g + 1], a1, bf[g][1], bf[g][3]);
                }
            }
        }
        __syncthreads();
    }

    // ---- epilogue: scale + bias, direct stores
    #pragma unroll
    for (int i = 0; i < 2; i++) {
        #pragma unroll
        for (int half = 0; half < 2; half++) {
            const int row = rowBase + wm * 32 + i * 16 + (lane >> 2) + half * 8;
            const float rb = (biasMode == 2) ? bias[row] : 0.0f;
            #pragma unroll
            for (int j = 0; j < 8; j++) {
                const int col = colBase + wn * 64 + j * 8 + (lane & 3) * 2;
                float v0 = acc[i][j][half * 2 + 0] * scale;
                float v1 = acc[i][j][half * 2 + 1] * scale;
                if (biasMode == 1) { v0 += bias[col]; v1 += bias[col + 1]; }
                else               { v0 += rb;        v1 += rb; }
                const size_t base = (size_t)row * ldc + col;
                if (outMode == 0) {
                    float2 o; o.x = v0; o.y = v1;
                    *(float2*)(Cf + base) = o;
                } else {
                    __nv_bfloat16 h0 = __float2bfloat16(v0);
                    __nv_bfloat16 h1 = __float2bfloat16(v1);
                    __nv_bfloat162 hh; hh.x = h0; hh.y = h1;
                    __nv_bfloat162 ll;
                    ll.x = __float2bfloat16(v0 - __bfloat162float(h0));
                    ll.y = __float2bfloat16(v1 - __bfloat162float(h1));
                    *(__nv_bfloat162*)(Ch + base) = hh;
                    *(__nv_bfloat162*)(Cl + base) = ll;
                }
            }
        }
    }
}

// ---------------------------------------------------------------------------
// split fp32 -> bf16 hi/lo
// ---------------------------------------------------------------------------
__global__ __launch_bounds__(256) void split_f32(
    const float* __restrict__ in, __nv_bfloat16* __restrict__ hi,
    __nv_bfloat16* __restrict__ lo, size_t n)
{
    size_t i = ((size_t)blockIdx.x * 256 + threadIdx.x) * 4;
    if (i >= n) return;
    float4 v = *(const float4*)(in + i);
    __nv_bfloat16 h0 = __float2bfloat16(v.x), h1 = __float2bfloat16(v.y);
    __nv_bfloat16 h2 = __float2bfloat16(v.z), h3 = __float2bfloat16(v.w);
    __nv_bfloat162 ha; ha.x = h0; ha.y = h1;
    __nv_bfloat162 hb; hb.x = h2; hb.y = h3;
    __nv_bfloat162 la, lb;
    la.x = __float2bfloat16(v.x - __bfloat162float(h0));
    la.y = __float2bfloat16(v.y - __bfloat162float(h1));
    lb.x = __float2bfloat16(v.z - __bfloat162float(h2));
    lb.y = __float2bfloat16(v.w - __bfloat162float(h3));
    *(__nv_bfloat162*)(hi + i) = ha; *(__nv_bfloat162*)(hi + i + 2) = hb;
    *(__nv_bfloat162*)(lo + i) = la; *(__nv_bfloat162*)(lo + i + 2) = lb;
}

// ---------------------------------------------------------------------------
// row softmax: fp32 in, bf16 hi/lo out. One block per row of 2048.
// ---------------------------------------------------------------------------
__global__ __launch_bounds__(256) void softmax_split(
    const float* __restrict__ P, __nv_bfloat16* __restrict__ Ph,
    __nv_bfloat16* __restrict__ Pl, int n)
{
    const float* row = P + (size_t)blockIdx.x * n;
    __nv_bfloat16* oh = Ph + (size_t)blockIdx.x * n;
    __nv_bfloat16* ol = Pl + (size_t)blockIdx.x * n;
    const int tid = threadIdx.x, lane = tid & 31, wd = tid >> 5;
    __shared__ float red[8];

    float v[8]; float m = -INFINITY;
    #pragma unroll
    for (int i = 0; i < 8; i++) { v[i] = row[tid + i * 256]; m = fmaxf(m, v[i]); }
    #pragma unroll
    for (int o = 16; o > 0; o >>= 1) m = fmaxf(m, __shfl_xor_sync(~0u, m, o));
    if (lane == 0) red[wd] = m;
    __syncthreads();
    float mb = red[0];
    #pragma unroll
    for (int w = 1; w < 8; w++) mb = fmaxf(mb, red[w]);
    __syncthreads();

    float s = 0.0f;
    #pragma unroll
    for (int i = 0; i < 8; i++) { v[i] = __expf(v[i] - mb); s += v[i]; }
    #pragma unroll
    for (int o = 16; o > 0; o >>= 1) s += __shfl_xor_sync(~0u, s, o);
    if (lane == 0) red[wd] = s;
    __syncthreads();
    float sb = 0.0f;
    #pragma unroll
    for (int w = 0; w < 8; w++) sb += red[w];
    const float r = 1.0f / sb;

    #pragma unroll
    for (int i = 0; i < 8; i++) {
        float p = v[i] * r;
        __nv_bfloat16 h = __float2bfloat16(p);
        oh[tid + i * 256] = h;
        ol[tid + i * 256] = __float2bfloat16(p - __bfloat162float(h));
    }
}

// ---------------------------------------------------------------------------
extern "C" void kernel_launch(void* const* d_in, const int* in_sizes, int n_in,
                              void* d_out, int out_size)
{
    (void)in_sizes; (void)n_in; (void)out_size;
    const float* x  = (const float*)d_in[0];
    const float* Wq = (const float*)d_in[1];
    const float* bq = (const float*)d_in[2];
    const float* Wk = (const float*)d_in[3];
    const float* bk = (const float*)d_in[4];
    const float* Wv = (const float*)d_in[5];
    const float* bv = (const float*)d_in[6];
    float* out = (float*)d_out;

    cudaFuncSetAttribute(mma_gemm, cudaFuncAttributeMaxDynamicSharedMemorySize,
                         2 * STAGE_BYTES);

    __nv_bfloat16 *xh, *xl, *Wqh, *Wql, *Wkh, *Wkl, *Wvh, *Wvl;
    __nv_bfloat16 *Qh, *Ql, *Kh, *Kl, *Vth, *Vtl, *Ph, *Pl;
    float *P;
    cudaGetSymbolAddress((void**)&xh, g_xh);   cudaGetSymbolAddress((void**)&xl, g_xl);
    cudaGetSymbolAddress((void**)&Wqh, g_Wqh); cudaGetSymbolAddress((void**)&Wql, g_Wql);
    cudaGetSymbolAddress((void**)&Wkh, g_Wkh); cudaGetSymbolAddress((void**)&Wkl, g_Wkl);
    cudaGetSymbolAddress((void**)&Wvh, g_Wvh); cudaGetSymbolAddress((void**)&Wvl, g_Wvl);
    cudaGetSymbolAddress((void**)&Qh, g_Qh);   cudaGetSymbolAddress((void**)&Ql, g_Ql);
    cudaGetSymbolAddress((void**)&Kh, g_KhA);  cudaGetSymbolAddress((void**)&Kl, g_KlA);
    cudaGetSymbolAddress((void**)&Vth, g_Vth); cudaGetSymbolAddress((void**)&Vtl, g_Vtl);
    cudaGetSymbolAddress((void**)&P, g_P);
    cudaGetSymbolAddress((void**)&Ph, g_Ph);   cudaGetSymbolAddress((void**)&Pl, g_Pl);

    const size_t nX = (size_t)MTOT * HN;
    const size_t nW = (size_t)HN * HN;
    const int smem = 2 * STAGE_BYTES;

    // 0) split inputs to bf16 hi/lo
    split_f32<<<(unsigned)(nX / 4 / 256), 256>>>(x,  xh,  xl,  nX);
    split_f32<<<(unsigned)(nW / 4 / 256), 256>>>(Wq, Wqh, Wql, nW);
    split_f32<<<(unsigned)(nW / 4 / 256), 256>>>(Wk, Wkh, Wkl, nW);
    split_f32<<<(unsigned)(nW / 4 / 256), 256>>>(Wv, Wvh, Wvl, nW);

    // 1) Q = x@Wq^T + bq,  K = x@Wk^T + bk   (split bf16 out)
    {
        dim3 g(HN / 128, MTOT / 128, 1);
        mma_gemm<<<g, 256, smem>>>(xh, xl, Wqh, Wql, bq, 1, 1.0f,
                                   nullptr, Qh, Ql, 1, HN, HN, 0, 0, 0);
        mma_gemm<<<g, 256, smem>>>(xh, xl, Wkh, Wkl, bk, 1, 1.0f,
                                   nullptr, Kh, Kl, 1, HN, HN, 0, 0, 0);
    }
    // 2) Vt_b = Wv @ x_b^T + bv[row]   (split bf16 out)  M=1024, N=2048 per batch
    {
        dim3 g(SN / 128, HN / 128, BN);
        mma_gemm<<<g, 256, smem>>>(Wvh, Wvl, xh, xl, bv, 2, 1.0f,
                                   nullptr, Vth, Vtl, 1, HN, SN,
                                   0, (size_t)SN * HN, (size_t)HN * SN);
    }
    // 3) scores = Q_b @ K_b^T / 32    (fp32 out)  M=N=2048, K=1024
    {
        dim3 g(SN / 128, SN / 128, BN);
        mma_gemm<<<g, 256, smem>>>(Qh, Ql, Kh, Kl, nullptr, 0, 0.03125f,
                                   P, nullptr, nullptr, 0, HN, SN,
                                   (size_t)SN * HN, (size_t)SN * HN, (size_t)SN * SN);
    }
    // 4) softmax rows -> split P
    softmax_split<<<BN * SN, 256>>>(P, Ph, Pl, SN);

    // 5) out = P_b @ Vt_b^T           (fp32 out)  M=2048, N=1024, K=2048
    {
        dim3 g(HN / 128, SN / 128, BN);
        mma_gemm<<<g, 256, smem>>>(Ph, Pl, Vth, Vtl, nullptr, 0, 1.0f,
                                   out, nullptr, nullptr, 0, SN, HN,
                                   (size_t)SN * SN, (size_t)HN * SN, (size_t)SN * HN);
    }
}

// round 4
// speedup vs baseline: 2.9815x; 1.0780x over previous
#include <cuda_runtime.h>
#include <cuda_bf16.h>
#include <math.h>
#include <stdint.h>

#define BN 4
#define SN 2048
#define HN 1024
#define MTOT (BN * SN)

// ---------------------------------------------------------------------------
// Scratch (__device__ globals; allocation-free rule)
// ---------------------------------------------------------------------------
__device__ __nv_bfloat16 g_xh[(size_t)MTOT * HN], g_xl[(size_t)MTOT * HN];
__device__ __nv_bfloat16 g_Wqh[(size_t)HN * HN], g_Wql[(size_t)HN * HN];
__device__ __nv_bfloat16 g_Wkh[(size_t)HN * HN], g_Wkl[(size_t)HN * HN];
__device__ __nv_bfloat16 g_Wvh[(size_t)HN * HN], g_Wvl[(size_t)HN * HN];
__device__ __nv_bfloat16 g_Qh[(size_t)MTOT * HN], g_Ql[(size_t)MTOT * HN];
__device__ __nv_bfloat16 g_KhA[(size_t)MTOT * HN], g_KlA[(size_t)MTOT * HN];
__device__ __nv_bfloat16 g_Vth[(size_t)BN * HN * SN], g_Vtl[(size_t)BN * HN * SN];
__device__ float         g_P[(size_t)BN * SN * SN];
__device__ __nv_bfloat16 g_Ph[(size_t)BN * SN * SN], g_Pl[(size_t)BN * SN * SN];

// ---------------------------------------------------------------------------
// Helpers (compute_103-safe: ldmatrix + mma.sync + cp.async only)
// ---------------------------------------------------------------------------
__device__ __forceinline__ uint32_t smem_u32(const void* p) {
    uint32_t a;
    asm("{ .reg .u64 t; cvta.to.shared.u64 t, %1; cvt.u32.u64 %0, t; }" : "=r"(a) : "l"(p));
    return a;
}
__device__ __forceinline__ void ldsm_x4(uint32_t* r, uint32_t a) {
    asm volatile("ldmatrix.sync.aligned.m8n8.x4.shared.b16 {%0,%1,%2,%3}, [%4];"
                 : "=r"(r[0]), "=r"(r[1]), "=r"(r[2]), "=r"(r[3]) : "r"(a));
}
__device__ __forceinline__ void mma_bf16(float* c, const uint32_t* a,
                                         uint32_t b0, uint32_t b1) {
    asm volatile("mma.sync.aligned.m16n8k16.row.col.f32.bf16.bf16.f32 "
                 "{%0,%1,%2,%3}, {%4,%5,%6,%7}, {%8,%9}, {%0,%1,%2,%3};"
                 : "+f"(c[0]), "+f"(c[1]), "+f"(c[2]), "+f"(c[3])
                 : "r"(a[0]), "r"(a[1]), "r"(a[2]), "r"(a[3]), "r"(b0), "r"(b1));
}
#define CP_COMMIT() asm volatile("cp.async.commit_group;" ::: "memory")
#define CP_WAIT1()  asm volatile("cp.async.wait_group 1;" ::: "memory")
#define CP_WAIT0()  asm volatile("cp.async.wait_group 0;" ::: "memory")

// ---------------------------------------------------------------------------
// NT GEMM via mma.sync bf16, 3-pass hi/lo split:
//   C[M,N] = scale * sum_k (Ah·Bh + Ah·Bl + Al·Bh) + bias
// Tile 128x128, BK=64 (128B rows, SW128 xor swizzle), 256 threads,
// warp grid 4(m) x 2(n), warp tile 32x64.
// 3-stage cp.async pipeline, fragments hoisted across the 3 split passes.
// biasMode: 0 none, 1 bias[col], 2 bias[row].  outMode: 0 fp32, 1 bf16 hi/lo.
// ---------------------------------------------------------------------------
#define TILE_BYTES  16384
#define STAGE_BYTES (4 * TILE_BYTES)
#define NSTAGE      3

__global__ __launch_bounds__(256, 1)
void mma_gemm(const __nv_bfloat16* __restrict__ Ah, const __nv_bfloat16* __restrict__ Al,
              const __nv_bfloat16* __restrict__ Bh, const __nv_bfloat16* __restrict__ Bl,
              const float* __restrict__ bias, int biasMode, float scale,
              float* __restrict__ Cf, __nv_bfloat16* __restrict__ Ch,
              __nv_bfloat16* __restrict__ Cl, int outMode, int K, int ldc,
              size_t szA, size_t szB, size_t szC)
{
    extern __shared__ char smem[];
    const uint32_t sb = smem_u32(smem);
    const int tid = threadIdx.x, lane = tid & 31, wid = tid >> 5;
    const int wm = wid & 3, wn = wid >> 2;

    Ah += (size_t)blockIdx.z * szA;  Al += (size_t)blockIdx.z * szA;
    Bh += (size_t)blockIdx.z * szB;  Bl += (size_t)blockIdx.z * szB;
    if (outMode == 0) Cf += (size_t)blockIdx.z * szC;
    else { Ch += (size_t)blockIdx.z * szC; Cl += (size_t)blockIdx.z * szC; }

    const int rowBase = blockIdx.y * 128;
    const int colBase = blockIdx.x * 128;

    const __nv_bfloat16* tAh = Ah + (size_t)rowBase * K;
    const __nv_bfloat16* tAl = Al + (size_t)rowBase * K;
    const __nv_bfloat16* tBh = Bh + (size_t)colBase * K;
    const __nv_bfloat16* tBl = Bl + (size_t)colBase * K;

    const int NK = K >> 6;

    // stage loader: 16B cp.async, SW128 swizzle
    auto load_tile = [&](uint32_t dst, const __nv_bfloat16* g) {
        #pragma unroll
        for (int i = 0; i < 4; i++) {
            int idx = i * 256 + tid;
            int row = idx >> 3;
            int kb  = idx & 7;
            uint32_t off = row * 128 + kb * 16;
            uint32_t sw  = off ^ ((off >> 3) & 0x70);
            const void* src = (const void*)(g + (size_t)row * K + kb * 8);
            asm volatile("cp.async.cg.shared.global [%0], [%1], 16;"
                         :: "r"(dst + sw), "l"(src));
        }
    };
    auto load_stage = [&](int buf, int c) {
        uint32_t st = sb + buf * STAGE_BYTES;
        size_t ko = (size_t)c * 64;
        load_tile(st,                  tAh + ko);
        load_tile(st + TILE_BYTES,     tAl + ko);
        load_tile(st + 2 * TILE_BYTES, tBh + ko);
        load_tile(st + 3 * TILE_BYTES, tBl + ko);
        CP_COMMIT();
    };

    float acc[2][8][4];
    #pragma unroll
    for (int i = 0; i < 2; i++)
        #pragma unroll
        for (int j = 0; j < 8; j++)
            #pragma unroll
            for (int q = 0; q < 4; q++) acc[i][j][q] = 0.0f;

    // ldmatrix lane addressing
    const int lm = lane & 15;
    const int lk = lane >> 4;
    int rA[2], rB[4];
    #pragma unroll
    for (int i = 0; i < 2; i++) rA[i] = wm * 32 + i * 16 + lm;
    #pragma unroll
    for (int g = 0; g < 4; g++) rB[g] = wn * 64 + g * 16 + lm;

    // prologue: fill 2 of 3 stages
    load_stage(0, 0);
    if (NK > 1) load_stage(1, 1);

    int buf = 0;
    for (int c = 0; c < NK; c++) {
        if (c < NK - 1) { CP_WAIT1(); } else { CP_WAIT0(); }
        __syncthreads();
        if (c + 2 < NK) {
            int nb = buf + 2; if (nb >= NSTAGE) nb -= NSTAGE;
            load_stage(nb, c + 2);
        }

        const uint32_t stage = sb + buf * STAGE_BYTES;
        #pragma unroll
        for (int ks = 0; ks < 4; ks++) {
            const int atom = ks * 2 + lk;
            // hoisted fragment loads (each used by 2 of the 3 passes)
            uint32_t ah0[4], ah1[4], al0[4], al1[4];
            ldsm_x4(ah0, stage + rA[0] * 128 + ((atom ^ (rA[0] & 7)) << 4));
            ldsm_x4(ah1, stage + rA[1] * 128 + ((atom ^ (rA[1] & 7)) << 4));
            ldsm_x4(al0, stage + TILE_BYTES + rA[0] * 128 + ((atom ^ (rA[0] & 7)) << 4));
            ldsm_x4(al1, stage + TILE_BYTES + rA[1] * 128 + ((atom ^ (rA[1] & 7)) << 4));
            uint32_t bh[4][4], bl[4][4];
            #pragma unroll
            for (int g = 0; g < 4; g++) {
                ldsm_x4(bh[g], stage + 2 * TILE_BYTES + rB[g] * 128 + ((atom ^ (rB[g] & 7)) << 4));
                ldsm_x4(bl[g], stage + 3 * TILE_BYTES + rB[g] * 128 + ((atom ^ (rB[g] & 7)) << 4));
            }
            // pass 0: Ah·Bh  (pass-major order spaces dependent MMAs by 16)
            #pragma unroll
            for (int g = 0; g < 4; g++) {
                mma_bf16(acc[0][2 * g + 0], ah0, bh[g][0], bh[g][2]);
                mma_bf16(acc[0][2 * g + 1], ah0, bh[g][1], bh[g][3]);
                mma_bf16(acc[1][2 * g + 0], ah1, bh[g][0], bh[g][2]);
                mma_bf16(acc[1][2 * g + 1], ah1, bh[g][1], bh[g][3]);
            }
            // pass 1: Ah·Bl
            #pragma unroll
            for (int g = 0; g < 4; g++) {
                mma_bf16(acc[0][2 * g + 0], ah0, bl[g][0], bl[g][2]);
                mma_bf16(acc[0][2 * g + 1], ah0, bl[g][1], bl[g][3]);
                mma_bf16(acc[1][2 * g + 0], ah1, bl[g][0], bl[g][2]);
                mma_bf16(acc[1][2 * g + 1], ah1, bl[g][1], bl[g][3]);
            }
            // pass 2: Al·Bh
            #pragma unroll
            for (int g = 0; g < 4; g++) {
                mma_bf16(acc[0][2 * g + 0], al0, bh[g][0], bh[g][2]);
                mma_bf16(acc[0][2 * g + 1], al0, bh[g][1], bh[g][3]);
                mma_bf16(acc[1][2 * g + 0], al1, bh[g][0], bh[g][2]);
                mma_bf16(acc[1][2 * g + 1], al1, bh[g][1], bh[g][3]);
            }
        }
        buf++; if (buf >= NSTAGE) buf = 0;
    }

    // epilogue: scale + bias, direct stores
    #pragma unroll
    for (int i = 0; i < 2; i++) {
        #pragma unroll
        for (int half = 0; half < 2; half++) {
            const int row = rowBase + wm * 32 + i * 16 + (lane >> 2) + half * 8;
            const float rb = (biasMode == 2) ? bias[row] : 0.0f;
            #pragma unroll
            for (int j = 0; j < 8; j++) {
                const int col = colBase + wn * 64 + j * 8 + (lane & 3) * 2;
                float v0 = acc[i][j][half * 2 + 0] * scale;
                float v1 = acc[i][j][half * 2 + 1] * scale;
                if (biasMode == 1) { v0 += bias[col]; v1 += bias[col + 1]; }
                else               { v0 += rb;        v1 += rb; }
                const size_t base = (size_t)row * ldc + col;
                if (outMode == 0) {
                    float2 o; o.x = v0; o.y = v1;
                    *(float2*)(Cf + base) = o;
                } else {
                    __nv_bfloat16 h0 = __float2bfloat16(v0);
                    __nv_bfloat16 h1 = __float2bfloat16(v1);
                    __nv_bfloat162 hh; hh.x = h0; hh.y = h1;
                    __nv_bfloat162 ll;
                    ll.x = __float2bfloat16(v0 - __bfloat162float(h0));
                    ll.y = __float2bfloat16(v1 - __bfloat162float(h1));
                    *(__nv_bfloat162*)(Ch + base) = hh;
                    *(__nv_bfloat162*)(Cl + base) = ll;
                }
            }
        }
    }
}

// ---------------------------------------------------------------------------
// split fp32 -> bf16 hi/lo
// ---------------------------------------------------------------------------
__global__ __launch_bounds__(256) void split_f32(
    const float* __restrict__ in, __nv_bfloat16* __restrict__ hi,
    __nv_bfloat16* __restrict__ lo, size_t n)
{
    size_t i = ((size_t)blockIdx.x * 256 + threadIdx.x) * 4;
    if (i >= n) return;
    float4 v = *(const float4*)(in + i);
    __nv_bfloat16 h0 = __float2bfloat16(v.x), h1 = __float2bfloat16(v.y);
    __nv_bfloat16 h2 = __float2bfloat16(v.z), h3 = __float2bfloat16(v.w);
    __nv_bfloat162 ha; ha.x = h0; ha.y = h1;
    __nv_bfloat162 hb; hb.x = h2; hb.y = h3;
    __nv_bfloat162 la, lb;
    la.x = __float2bfloat16(v.x - __bfloat162float(h0));
    la.y = __float2bfloat16(v.y - __bfloat162float(h1));
    lb.x = __float2bfloat16(v.z - __bfloat162float(h2));
    lb.y = __float2bfloat16(v.w - __bfloat162float(h3));
    *(__nv_bfloat162*)(hi + i) = ha; *(__nv_bfloat162*)(hi + i + 2) = hb;
    *(__nv_bfloat162*)(lo + i) = la; *(__nv_bfloat162*)(lo + i + 2) = lb;
}

// ---------------------------------------------------------------------------
// row softmax: fp32 in, bf16 hi/lo out. One block per row of 2048.
// ---------------------------------------------------------------------------
__global__ __launch_bounds__(256) void softmax_split(
    const float* __restrict__ P, __nv_bfloat16* __restrict__ Ph,
    __nv_bfloat16* __restrict__ Pl, int n)
{
    const float* row = P + (size_t)blockIdx.x * n;
    __nv_bfloat16* oh = Ph + (size_t)blockIdx.x * n;
    __nv_bfloat16* ol = Pl + (size_t)blockIdx.x * n;
    const int tid = threadIdx.x, lane = tid & 31, wd = tid >> 5;
    __shared__ float red[8];

    float v[8]; float m = -INFINITY;
    #pragma unroll
    for (int i = 0; i < 8; i++) { v[i] = row[tid + i * 256]; m = fmaxf(m, v[i]); }
    #pragma unroll
    for (int o = 16; o > 0; o >>= 1) m = fmaxf(m, __shfl_xor_sync(~0u, m, o));
    if (lane == 0) red[wd] = m;
    __syncthreads();
    float mb = red[0];
    #pragma unroll
    for (int w = 1; w < 8; w++) mb = fmaxf(mb, red[w]);
    __syncthreads();

    float s = 0.0f;
    #pragma unroll
    for (int i = 0; i < 8; i++) { v[i] = __expf(v[i] - mb); s += v[i]; }
    #pragma unroll
    for (int o = 16; o > 0; o >>= 1) s += __shfl_xor_sync(~0u, s, o);
    if (lane == 0) red[wd] = s;
    __syncthreads();
    float sb = 0.0f;
    #pragma unroll
    for (int w = 0; w < 8; w++) sb += red[w];
    const float r = 1.0f / sb;

    #pragma unroll
    for (int i = 0; i < 8; i++) {
        float p = v[i] * r;
        __nv_bfloat16 h = __float2bfloat16(p);
        oh[tid + i * 256] = h;
        ol[tid + i * 256] = __float2bfloat16(p - __bfloat162float(h));
    }
}

// ---------------------------------------------------------------------------
extern "C" void kernel_launch(void* const* d_in, const int* in_sizes, int n_in,
                              void* d_out, int out_size)
{
    (void)in_sizes; (void)n_in; (void)out_size;
    const float* x  = (const float*)d_in[0];
    const float* Wq = (const float*)d_in[1];
    const float* bq = (const float*)d_in[2];
    const float* Wk = (const float*)d_in[3];
    const float* bk = (const float*)d_in[4];
    const float* Wv = (const float*)d_in[5];
    const float* bv = (const float*)d_in[6];
    float* out = (float*)d_out;

    cudaFuncSetAttribute(mma_gemm, cudaFuncAttributeMaxDynamicSharedMemorySize,
                         NSTAGE * STAGE_BYTES);

    __nv_bfloat16 *xh, *xl, *Wqh, *Wql, *Wkh, *Wkl, *Wvh, *Wvl;
    __nv_bfloat16 *Qh, *Ql, *Kh, *Kl, *Vth, *Vtl, *Ph, *Pl;
    float *P;
    cudaGetSymbolAddress((void**)&xh, g_xh);   cudaGetSymbolAddress((void**)&xl, g_xl);
    cudaGetSymbolAddress((void**)&Wqh, g_Wqh); cudaGetSymbolAddress((void**)&Wql, g_Wql);
    cudaGetSymbolAddress((void**)&Wkh, g_Wkh); cudaGetSymbolAddress((void**)&Wkl, g_Wkl);
    cudaGetSymbolAddress((void**)&Wvh, g_Wvh); cudaGetSymbolAddress((void**)&Wvl, g_Wvl);
    cudaGetSymbolAddress((void**)&Qh, g_Qh);   cudaGetSymbolAddress((void**)&Ql, g_Ql);
    cudaGetSymbolAddress((void**)&Kh, g_KhA);  cudaGetSymbolAddress((void**)&Kl, g_KlA);
    cudaGetSymbolAddress((void**)&Vth, g_Vth); cudaGetSymbolAddress((void**)&Vtl, g_Vtl);
    cudaGetSymbolAddress((void**)&P, g_P);
    cudaGetSymbolAddress((void**)&Ph, g_Ph);   cudaGetSymbolAddress((void**)&Pl, g_Pl);

    const size_t nX = (size_t)MTOT * HN;
    const size_t nW = (size_t)HN * HN;
    const int smem = NSTAGE * STAGE_BYTES;

    // 0) split inputs to bf16 hi/lo
    split_f32<<<(unsigned)(nX / 4 / 256), 256>>>(x,  xh,  xl,  nX);
    split_f32<<<(unsigned)(nW / 4 / 256), 256>>>(Wq, Wqh, Wql, nW);
    split_f32<<<(unsigned)(nW / 4 / 256), 256>>>(Wk, Wkh, Wkl, nW);
    split_f32<<<(unsigned)(nW / 4 / 256), 256>>>(Wv, Wvh, Wvl, nW);

    // 1) Q = x@Wq^T + bq,  K = x@Wk^T + bk   (split bf16 out)
    {
        dim3 g(HN / 128, MTOT / 128, 1);
        mma_gemm<<<g, 256, smem>>>(xh, xl, Wqh, Wql, bq, 1, 1.0f,
                                   nullptr, Qh, Ql, 1, HN, HN, 0, 0, 0);
        mma_gemm<<<g, 256, smem>>>(xh, xl, Wkh, Wkl, bk, 1, 1.0f,
                                   nullptr, Kh, Kl, 1, HN, HN, 0, 0, 0);
    }
    // 2) Vt_b = Wv @ x_b^T + bv[row]   (split bf16 out)
    {
        dim3 g(SN / 128, HN / 128, BN);
        mma_gemm<<<g, 256, smem>>>(Wvh, Wvl, xh, xl, bv, 2, 1.0f,
                                   nullptr, Vth, Vtl, 1, HN, SN,
                                   0, (size_t)SN * HN, (size_t)HN * SN);
    }
    // 3) scores = Q_b @ K_b^T / 32    (fp32 out)
    {
        dim3 g(SN / 128, SN / 128, BN);
        mma_gemm<<<g, 256, smem>>>(Qh, Ql, Kh, Kl, nullptr, 0, 0.03125f,
                                   P, nullptr, nullptr, 0, HN, SN,
                                   (size_t)SN * HN, (size_t)SN * HN, (size_t)SN * SN);
    }
    // 4) softmax rows -> split P
    softmax_split<<<BN * SN, 256>>>(P, Ph, Pl, SN);

    // 5) out = P_b @ Vt_b^T           (fp32 out)
    {
        dim3 g(HN / 128, SN / 128, BN);
        mma_gemm<<<g, 256, smem>>>(Ph, Pl, Vth, Vtl, nullptr, 0, 1.0f,
                                   out, nullptr, nullptr, 0, SN, HN,
                                   (size_t)SN * SN, (size_t)HN * SN, (size_t)SN * HN);
    }
}

// round 5
// speedup vs baseline: 2.9853x; 1.0013x over previous
#include <cuda_runtime.h>
#include <cuda_bf16.h>
#include <math.h>
#include <stdint.h>

#define BN 4
#define SN 2048
#define HN 1024
#define MTOT (BN * SN)

// ---------------------------------------------------------------------------
// Scratch (__device__ globals; allocation-free rule)
// ---------------------------------------------------------------------------
__device__ __nv_bfloat16 g_xh[(size_t)MTOT * HN], g_xl[(size_t)MTOT * HN];
__device__ __nv_bfloat16 g_Wqh[(size_t)HN * HN], g_Wql[(size_t)HN * HN];
__device__ __nv_bfloat16 g_Wkh[(size_t)HN * HN], g_Wkl[(size_t)HN * HN];
__device__ __nv_bfloat16 g_Wvh[(size_t)HN * HN], g_Wvl[(size_t)HN * HN];
__device__ __nv_bfloat16 g_Qh[(size_t)MTOT * HN], g_Ql[(size_t)MTOT * HN];
__device__ __nv_bfloat16 g_KhA[(size_t)MTOT * HN], g_KlA[(size_t)MTOT * HN];
__device__ __nv_bfloat16 g_Vth[(size_t)BN * HN * SN], g_Vtl[(size_t)BN * HN * SN];
__device__ float         g_P[(size_t)BN * SN * SN];
__device__ __nv_bfloat16 g_Ph[(size_t)BN * SN * SN], g_Pl[(size_t)BN * SN * SN];

// ---------------------------------------------------------------------------
// Helpers (compute_103-safe: ldmatrix + mma.sync + cp.async only)
// ---------------------------------------------------------------------------
__device__ __forceinline__ uint32_t smem_u32(const void* p) {
    uint32_t a;
    asm("{ .reg .u64 t; cvta.to.shared.u64 t, %1; cvt.u32.u64 %0, t; }" : "=r"(a) : "l"(p));
    return a;
}
__device__ __forceinline__ void ldsm_x4(uint32_t* r, uint32_t a) {
    asm volatile("ldmatrix.sync.aligned.m8n8.x4.shared.b16 {%0,%1,%2,%3}, [%4];"
                 : "=r"(r[0]), "=r"(r[1]), "=r"(r[2]), "=r"(r[3]) : "r"(a));
}
__device__ __forceinline__ void mma_bf16(float* c, const uint32_t* a,
                                         uint32_t b0, uint32_t b1) {
    asm volatile("mma.sync.aligned.m16n8k16.row.col.f32.bf16.bf16.f32 "
                 "{%0,%1,%2,%3}, {%4,%5,%6,%7}, {%8,%9}, {%0,%1,%2,%3};"
                 : "+f"(c[0]), "+f"(c[1]), "+f"(c[2]), "+f"(c[3])
                 : "r"(a[0]), "r"(a[1]), "r"(a[2]), "r"(a[3]), "r"(b0), "r"(b1));
}
#define CP_COMMIT() asm volatile("cp.async.commit_group;" ::: "memory")
#define CP_WAIT1()  asm volatile("cp.async.wait_group 1;" ::: "memory")
#define CP_WAIT0()  asm volatile("cp.async.wait_group 0;" ::: "memory")

// ---------------------------------------------------------------------------
// NT GEMM via mma.sync bf16, 3-pass hi/lo split:
//   C[M,N] = scale * sum_k (Ah·Bh + Ah·Bl + Al·Bh) + bias
// Tile 128x128, BK=64 (128B rows, SW128 xor swizzle), 512 threads,
// warp grid 4(m) x 4(n), warp tile 32x32. 3-stage cp.async pipeline,
// fragments hoisted across the 3 split passes.
// biasMode: 0 none, 1 bias[col], 2 bias[row].  outMode: 0 fp32, 1 bf16 hi/lo.
// ---------------------------------------------------------------------------
#define TILE_BYTES  16384
#define STAGE_BYTES (4 * TILE_BYTES)
#define NSTAGE      3

__global__ __launch_bounds__(512, 1)
void mma_gemm(const __nv_bfloat16* __restrict__ Ah, const __nv_bfloat16* __restrict__ Al,
              const __nv_bfloat16* __restrict__ Bh, const __nv_bfloat16* __restrict__ Bl,
              const float* __restrict__ bias, int biasMode, float scale,
              float* __restrict__ Cf, __nv_bfloat16* __restrict__ Ch,
              __nv_bfloat16* __restrict__ Cl, int outMode, int K, int ldc,
              size_t szA, size_t szB, size_t szC)
{
    extern __shared__ char smem[];
    const uint32_t sb = smem_u32(smem);
    const int tid = threadIdx.x, lane = tid & 31, wid = tid >> 5;
    const int wm = wid & 3, wn = wid >> 2;   // 4 x 4 warp grid

    Ah += (size_t)blockIdx.z * szA;  Al += (size_t)blockIdx.z * szA;
    Bh += (size_t)blockIdx.z * szB;  Bl += (size_t)blockIdx.z * szB;
    if (outMode == 0) Cf += (size_t)blockIdx.z * szC;
    else { Ch += (size_t)blockIdx.z * szC; Cl += (size_t)blockIdx.z * szC; }

    const int rowBase = blockIdx.y * 128;
    const int colBase = blockIdx.x * 128;

    const __nv_bfloat16* tAh = Ah + (size_t)rowBase * K;
    const __nv_bfloat16* tAl = Al + (size_t)rowBase * K;
    const __nv_bfloat16* tBh = Bh + (size_t)colBase * K;
    const __nv_bfloat16* tBl = Bl + (size_t)colBase * K;

    const int NK = K >> 6;

    // stage loader: 16B cp.async, SW128 swizzle (512 threads -> 2 iters/tile)
    auto load_tile = [&](uint32_t dst, const __nv_bfloat16* g) {
        #pragma unroll
        for (int i = 0; i < 2; i++) {
            int idx = i * 512 + tid;
            int row = idx >> 3;
            int kb  = idx & 7;
            uint32_t off = row * 128 + kb * 16;
            uint32_t sw  = off ^ ((off >> 3) & 0x70);
            const void* src = (const void*)(g + (size_t)row * K + kb * 8);
            asm volatile("cp.async.cg.shared.global [%0], [%1], 16;"
                         :: "r"(dst + sw), "l"(src));
        }
    };
    auto load_stage = [&](int buf, int c) {
        uint32_t st = sb + buf * STAGE_BYTES;
        size_t ko = (size_t)c * 64;
        load_tile(st,                  tAh + ko);
        load_tile(st + TILE_BYTES,     tAl + ko);
        load_tile(st + 2 * TILE_BYTES, tBh + ko);
        load_tile(st + 3 * TILE_BYTES, tBl + ko);
        CP_COMMIT();
    };

    // accumulators: 2 m16-tiles x 4 n8-cols x 4
    float acc[2][4][4];
    #pragma unroll
    for (int i = 0; i < 2; i++)
        #pragma unroll
        for (int j = 0; j < 4; j++)
            #pragma unroll
            for (int q = 0; q < 4; q++) acc[i][j][q] = 0.0f;

    // ldmatrix lane addressing
    const int lm = lane & 15;
    const int lk = lane >> 4;
    int rA[2], rB[2];
    #pragma unroll
    for (int i = 0; i < 2; i++) rA[i] = wm * 32 + i * 16 + lm;
    #pragma unroll
    for (int g = 0; g < 2; g++) rB[g] = wn * 32 + g * 16 + lm;

    // prologue: fill 2 of 3 stages
    load_stage(0, 0);
    if (NK > 1) load_stage(1, 1);

    int buf = 0;
    for (int c = 0; c < NK; c++) {
        if (c < NK - 1) { CP_WAIT1(); } else { CP_WAIT0(); }
        __syncthreads();
        if (c + 2 < NK) {
            int nb = buf + 2; if (nb >= NSTAGE) nb -= NSTAGE;
            load_stage(nb, c + 2);
        }

        const uint32_t stage = sb + buf * STAGE_BYTES;
        #pragma unroll
        for (int ks = 0; ks < 4; ks++) {
            const int atom = ks * 2 + lk;
            // hoisted fragments (each used by 2 of the 3 passes)
            uint32_t ah0[4], ah1[4], al0[4], al1[4];
            ldsm_x4(ah0, stage + rA[0] * 128 + ((atom ^ (rA[0] & 7)) << 4));
            ldsm_x4(ah1, stage + rA[1] * 128 + ((atom ^ (rA[1] & 7)) << 4));
            ldsm_x4(al0, stage + TILE_BYTES + rA[0] * 128 + ((atom ^ (rA[0] & 7)) << 4));
            ldsm_x4(al1, stage + TILE_BYTES + rA[1] * 128 + ((atom ^ (rA[1] & 7)) << 4));
            uint32_t bh[2][4], bl[2][4];
            #pragma unroll
            for (int g = 0; g < 2; g++) {
                ldsm_x4(bh[g], stage + 2 * TILE_BYTES + rB[g] * 128 + ((atom ^ (rB[g] & 7)) << 4));
                ldsm_x4(bl[g], stage + 3 * TILE_BYTES + rB[g] * 128 + ((atom ^ (rB[g] & 7)) << 4));
            }
            // pass 0: Ah·Bh
            #pragma unroll
            for (int g = 0; g < 2; g++) {
                mma_bf16(acc[0][2 * g + 0], ah0, bh[g][0], bh[g][2]);
                mma_bf16(acc[0][2 * g + 1], ah0, bh[g][1], bh[g][3]);
                mma_bf16(acc[1][2 * g + 0], ah1, bh[g][0], bh[g][2]);
                mma_bf16(acc[1][2 * g + 1], ah1, bh[g][1], bh[g][3]);
            }
            // pass 1: Ah·Bl
            #pragma unroll
            for (int g = 0; g < 2; g++) {
                mma_bf16(acc[0][2 * g + 0], ah0, bl[g][0], bl[g][2]);
                mma_bf16(acc[0][2 * g + 1], ah0, bl[g][1], bl[g][3]);
                mma_bf16(acc[1][2 * g + 0], ah1, bl[g][0], bl[g][2]);
                mma_bf16(acc[1][2 * g + 1], ah1, bl[g][1], bl[g][3]);
            }
            // pass 2: Al·Bh
            #pragma unroll
            for (int g = 0; g < 2; g++) {
                mma_bf16(acc[0][2 * g + 0], al0, bh[g][0], bh[g][2]);
                mma_bf16(acc[0][2 * g + 1], al0, bh[g][1], bh[g][3]);
                mma_bf16(acc[1][2 * g + 0], al1, bh[g][0], bh[g][2]);
                mma_bf16(acc[1][2 * g + 1], al1, bh[g][1], bh[g][3]);
            }
        }
        buf++; if (buf >= NSTAGE) buf = 0;
    }

    // epilogue: scale + bias, direct stores
    #pragma unroll
    for (int i = 0; i < 2; i++) {
        #pragma unroll
        for (int half = 0; half < 2; half++) {
            const int row = rowBase + wm * 32 + i * 16 + (lane >> 2) + half * 8;
            const float rb = (biasMode == 2) ? bias[row] : 0.0f;
            #pragma unroll
            for (int j = 0; j < 4; j++) {
                const int col = colBase + wn * 32 + j * 8 + (lane & 3) * 2;
                float v0 = acc[i][j][half * 2 + 0] * scale;
                float v1 = acc[i][j][half * 2 + 1] * scale;
                if (biasMode == 1) { v0 += bias[col]; v1 += bias[col + 1]; }
                else               { v0 += rb;        v1 += rb; }
                const size_t base = (size_t)row * ldc + col;
                if (outMode == 0) {
                    float2 o; o.x = v0; o.y = v1;
                    *(float2*)(Cf + base) = o;
                } else {
                    __nv_bfloat16 h0 = __float2bfloat16(v0);
                    __nv_bfloat16 h1 = __float2bfloat16(v1);
                    __nv_bfloat162 hh; hh.x = h0; hh.y = h1;
                    __nv_bfloat162 ll;
                    ll.x = __float2bfloat16(v0 - __bfloat162float(h0));
                    ll.y = __float2bfloat16(v1 - __bfloat162float(h1));
                    *(__nv_bfloat162*)(Ch + base) = hh;
                    *(__nv_bfloat162*)(Cl + base) = ll;
                }
            }
        }
    }
}

// ---------------------------------------------------------------------------
// split fp32 -> bf16 hi/lo
// ---------------------------------------------------------------------------
__global__ __launch_bounds__(256) void split_f32(
    const float* __restrict__ in, __nv_bfloat16* __restrict__ hi,
    __nv_bfloat16* __restrict__ lo, size_t n)
{
    size_t i = ((size_t)blockIdx.x * 256 + threadIdx.x) * 4;
    if (i >= n) return;
    float4 v = *(const float4*)(in + i);
    __nv_bfloat16 h0 = __float2bfloat16(v.x), h1 = __float2bfloat16(v.y);
    __nv_bfloat16 h2 = __float2bfloat16(v.z), h3 = __float2bfloat16(v.w);
    __nv_bfloat162 ha; ha.x = h0; ha.y = h1;
    __nv_bfloat162 hb; hb.x = h2; hb.y = h3;
    __nv_bfloat162 la, lb;
    la.x = __float2bfloat16(v.x - __bfloat162float(h0));
    la.y = __float2bfloat16(v.y - __bfloat162float(h1));
    lb.x = __float2bfloat16(v.z - __bfloat162float(h2));
    lb.y = __float2bfloat16(v.w - __bfloat162float(h3));
    *(__nv_bfloat162*)(hi + i) = ha; *(__nv_bfloat162*)(hi + i + 2) = hb;
    *(__nv_bfloat162*)(lo + i) = la; *(__nv_bfloat162*)(lo + i + 2) = lb;
}

// ---------------------------------------------------------------------------
// row softmax: fp32 in, bf16 hi/lo out. One block per row of 2048.
// ---------------------------------------------------------------------------
__global__ __launch_bounds__(256) void softmax_split(
    const float* __restrict__ P, __nv_bfloat16* __restrict__ Ph,
    __nv_bfloat16* __restrict__ Pl, int n)
{
    const float* row = P + (size_t)blockIdx.x * n;
    __nv_bfloat16* oh = Ph + (size_t)blockIdx.x * n;
    __nv_bfloat16* ol = Pl + (size_t)blockIdx.x * n;
    const int tid = threadIdx.x, lane = tid & 31, wd = tid >> 5;
    __shared__ float red[8];

    float v[8]; float m = -INFINITY;
    #pragma unroll
    for (int i = 0; i < 8; i++) { v[i] = row[tid + i * 256]; m = fmaxf(m, v[i]); }
    #pragma unroll
    for (int o = 16; o > 0; o >>= 1) m = fmaxf(m, __shfl_xor_sync(~0u, m, o));
    if (lane == 0) red[wd] = m;
    __syncthreads();
    float mb = red[0];
    #pragma unroll
    for (int w = 1; w < 8; w++) mb = fmaxf(mb, red[w]);
    __syncthreads();

    float s = 0.0f;
    #pragma unroll
    for (int i = 0; i < 8; i++) { v[i] = __expf(v[i] - mb); s += v[i]; }
    #pragma unroll
    for (int o = 16; o > 0; o >>= 1) s += __shfl_xor_sync(~0u, s, o);
    if (lane == 0) red[wd] = s;
    __syncthreads();
    float sb = 0.0f;
    #pragma unroll
    for (int w = 0; w < 8; w++) sb += red[w];
    const float r = 1.0f / sb;

    #pragma unroll
    for (int i = 0; i < 8; i++) {
        float p = v[i] * r;
        __nv_bfloat16 h = __float2bfloat16(p);
        oh[tid + i * 256] = h;
        ol[tid + i * 256] = __float2bfloat16(p - __bfloat162float(h));
    }
}

// ---------------------------------------------------------------------------
extern "C" void kernel_launch(void* const* d_in, const int* in_sizes, int n_in,
                              void* d_out, int out_size)
{
    (void)in_sizes; (void)n_in; (void)out_size;
    const float* x  = (const float*)d_in[0];
    const float* Wq = (const float*)d_in[1];
    const float* bq = (const float*)d_in[2];
    const float* Wk = (const float*)d_in[3];
    const float* bk = (const float*)d_in[4];
    const float* Wv = (const float*)d_in[5];
    const float* bv = (const float*)d_in[6];
    float* out = (float*)d_out;

    cudaFuncSetAttribute(mma_gemm, cudaFuncAttributeMaxDynamicSharedMemorySize,
                         NSTAGE * STAGE_BYTES);

    __nv_bfloat16 *xh, *xl, *Wqh, *Wql, *Wkh, *Wkl, *Wvh, *Wvl;
    __nv_bfloat16 *Qh, *Ql, *Kh, *Kl, *Vth, *Vtl, *Ph, *Pl;
    float *P;
    cudaGetSymbolAddress((void**)&xh, g_xh);   cudaGetSymbolAddress((void**)&xl, g_xl);
    cudaGetSymbolAddress((void**)&Wqh, g_Wqh); cudaGetSymbolAddress((void**)&Wql, g_Wql);
    cudaGetSymbolAddress((void**)&Wkh, g_Wkh); cudaGetSymbolAddress((void**)&Wkl, g_Wkl);
    cudaGetSymbolAddress((void**)&Wvh, g_Wvh); cudaGetSymbolAddress((void**)&Wvl, g_Wvl);
    cudaGetSymbolAddress((void**)&Qh, g_Qh);   cudaGetSymbolAddress((void**)&Ql, g_Ql);
    cudaGetSymbolAddress((void**)&Kh, g_KhA);  cudaGetSymbolAddress((void**)&Kl, g_KlA);
    cudaGetSymbolAddress((void**)&Vth, g_Vth); cudaGetSymbolAddress((void**)&Vtl, g_Vtl);
    cudaGetSymbolAddress((void**)&P, g_P);
    cudaGetSymbolAddress((void**)&Ph, g_Ph);   cudaGetSymbolAddress((void**)&Pl, g_Pl);

    const size_t nX = (size_t)MTOT * HN;
    const size_t nW = (size_t)HN * HN;
    const int smem = NSTAGE * STAGE_BYTES;

    // 0) split inputs to bf16 hi/lo
    split_f32<<<(unsigned)(nX / 4 / 256), 256>>>(x,  xh,  xl,  nX);
    split_f32<<<(unsigned)(nW / 4 / 256), 256>>>(Wq, Wqh, Wql, nW);
    split_f32<<<(unsigned)(nW / 4 / 256), 256>>>(Wk, Wkh, Wkl, nW);
    split_f32<<<(unsigned)(nW / 4 / 256), 256>>>(Wv, Wvh, Wvl, nW);

    // 1) Q = x@Wq^T + bq,  K = x@Wk^T + bk   (split bf16 out)
    {
        dim3 g(HN / 128, MTOT / 128, 1);
        mma_gemm<<<g, 512, smem>>>(xh, xl, Wqh, Wql, bq, 1, 1.0f,
                                   nullptr, Qh, Ql, 1, HN, HN, 0, 0, 0);
        mma_gemm<<<g, 512, smem>>>(xh, xl, Wkh, Wkl, bk, 1, 1.0f,
                                   nullptr, Kh, Kl, 1, HN, HN, 0, 0, 0);
    }
    // 2) Vt_b = Wv @ x_b^T + bv[row]   (split bf16 out)
    {
        dim3 g(SN / 128, HN / 128, BN);
        mma_gemm<<<g, 512, smem>>>(Wvh, Wvl, xh, xl, bv, 2, 1.0f,
                                   nullptr, Vth, Vtl, 1, HN, SN,
                                   0, (size_t)SN * HN, (size_t)HN * SN);
    }
    // 3) scores = Q_b @ K_b^T / 32    (fp32 out)
    {
        dim3 g(SN / 128, SN / 128, BN);
        mma_gemm<<<g, 512, smem>>>(Qh, Ql, Kh, Kl, nullptr, 0, 0.03125f,
                                   P, nullptr, nullptr, 0, HN, SN,
                                   (size_t)SN * HN, (size_t)SN * HN, (size_t)SN * SN);
    }
    // 4) softmax rows -> split P
    softmax_split<<<BN * SN, 256>>>(P, Ph, Pl, SN);

    // 5) out = P_b @ Vt_b^T           (fp32 out)
    {
        dim3 g(HN / 128, SN / 128, BN);
        mma_gemm<<<g, 512, smem>>>(Ph, Pl, Vth, Vtl, nullptr, 0, 1.0f,
                                   out, nullptr, nullptr, 0, SN, HN,
                                   (size_t)SN * SN, (size_t)HN * SN, (size_t)SN * HN);
    }
}

// round 9
// speedup vs baseline: 4.1636x; 1.3947x over previous
#include <cuda_runtime.h>
#include <cuda_fp16.h>
#include <math.h>
#include <stdint.h>

#define BN 4
#define SN 2048
#define HN 1024
#define MTOT (BN * SN)

// ---------------------------------------------------------------------------
// Scratch (__device__ globals; allocation-free rule)
// ---------------------------------------------------------------------------
__device__ __half g_xh[(size_t)MTOT * HN], g_xl[(size_t)MTOT * HN];
__device__ __half g_Wqh[(size_t)HN * HN], g_Wql[(size_t)HN * HN];
__device__ __half g_Wkh[(size_t)HN * HN], g_Wkl[(size_t)HN * HN];
__device__ __half g_Wvh[(size_t)HN * HN];
__device__ __half g_Qh[(size_t)MTOT * HN];
__device__ __half g_KhA[(size_t)MTOT * HN], g_KlA[(size_t)MTOT * HN];
__device__ __half g_Vth[(size_t)BN * HN * SN], g_Vtl[(size_t)BN * HN * SN];
__device__ float  g_P[(size_t)BN * SN * SN];
__device__ __half g_Ph[(size_t)BN * SN * SN];

// ---------------------------------------------------------------------------
// Helpers (compute_103-safe: ldmatrix + mma.sync + cp.async only)
// ---------------------------------------------------------------------------
__device__ __forceinline__ uint32_t smem_u32(const void* p) {
    uint32_t a;
    asm("{ .reg .u64 t; cvta.to.shared.u64 t, %1; cvt.u32.u64 %0, t; }" : "=r"(a) : "l"(p));
    return a;
}
__device__ __forceinline__ void ldsm_x4(uint32_t* r, uint32_t a) {
    asm volatile("ldmatrix.sync.aligned.m8n8.x4.shared.b16 {%0,%1,%2,%3}, [%4];"
                 : "=r"(r[0]), "=r"(r[1]), "=r"(r[2]), "=r"(r[3]) : "r"(a));
}
__device__ __forceinline__ void mma_f16(float* c, const uint32_t* a,
                                        uint32_t b0, uint32_t b1) {
    asm volatile("mma.sync.aligned.m16n8k16.row.col.f32.f16.f16.f32 "
                 "{%0,%1,%2,%3}, {%4,%5,%6,%7}, {%8,%9}, {%0,%1,%2,%3};"
                 : "+f"(c[0]), "+f"(c[1]), "+f"(c[2]), "+f"(c[3])
                 : "r"(a[0]), "r"(a[1]), "r"(a[2]), "r"(a[3]), "r"(b0), "r"(b1));
}
#define CP_COMMIT() asm volatile("cp.async.commit_group;" ::: "memory")
#define CP_WAIT1()  asm volatile("cp.async.wait_group 1;" ::: "memory")
#define CP_WAIT0()  asm volatile("cp.async.wait_group 0;" ::: "memory")

// ---------------------------------------------------------------------------
// NT GEMM via mma.sync fp16, 2-pass split-B:
//   C[M,N] = scale * sum_k A[m,k]*(Bh+Bl)[n,k] + bias
// (A unsplit fp16 carries one rounding; B near-exact via hi+lo.)
// Tile 128x128, BK=64 (128B rows, SW128 xor swizzle), 512 threads,
// warp grid 4(m) x 4(n), warp tile 32x32. 3-stage cp.async pipeline.
// biasMode: 0 none, 1 bias[col], 2 bias[row].
// outMode: 0 fp32, 1 fp16 hi only, 2 fp16 hi+lo.
// ---------------------------------------------------------------------------
#define TILE_BYTES  16384
#define STAGE_BYTES (3 * TILE_BYTES)
#define NSTAGE      3

__global__ __launch_bounds__(512, 1)
void mma_gemm(const __half* __restrict__ A, const __half* __restrict__ Bh,
              const __half* __restrict__ Bl,
              const float* __restrict__ bias, int biasMode, float scale,
              float* __restrict__ Cf, __half* __restrict__ Ch,
              __half* __restrict__ Cl, int outMode, int K, int ldc,
              size_t szA, size_t szB, size_t szC)
{
    extern __shared__ char smem[];
    const uint32_t sb = smem_u32(smem);
    const int tid = threadIdx.x, lane = tid & 31, wid = tid >> 5;
    const int wm = wid & 3, wn = wid >> 2;   // 4 x 4 warp grid

    A  += (size_t)blockIdx.z * szA;
    Bh += (size_t)blockIdx.z * szB;  Bl += (size_t)blockIdx.z * szB;
    if (outMode == 0) Cf += (size_t)blockIdx.z * szC;
    else { Ch += (size_t)blockIdx.z * szC; if (outMode == 2) Cl += (size_t)blockIdx.z * szC; }

    const int rowBase = blockIdx.y * 128;
    const int colBase = blockIdx.x * 128;

    const __half* tA  = A  + (size_t)rowBase * K;
    const __half* tBh = Bh + (size_t)colBase * K;
    const __half* tBl = Bl + (size_t)colBase * K;

    const int NK = K >> 6;

    // stage loader: 16B cp.async, SW128 swizzle (512 threads -> 2 iters/tile)
    auto load_tile = [&](uint32_t dst, const __half* g) {
        #pragma unroll
        for (int i = 0; i < 2; i++) {
            int idx = i * 512 + tid;
            int row = idx >> 3;
            int kb  = idx & 7;
            uint32_t off = row * 128 + kb * 16;
            uint32_t sw  = off ^ ((off >> 3) & 0x70);
            const void* src = (const void*)(g + (size_t)row * K + kb * 8);
            asm volatile("cp.async.cg.shared.global [%0], [%1], 16;"
                         :: "r"(dst + sw), "l"(src));
        }
    };
    auto load_stage = [&](int buf, int c) {
        uint32_t st = sb + buf * STAGE_BYTES;
        size_t ko = (size_t)c * 64;
        load_tile(st,                  tA  + ko);
        load_tile(st + TILE_BYTES,     tBh + ko);
        load_tile(st + 2 * TILE_BYTES, tBl + ko);
        CP_COMMIT();
    };

    // accumulators: 2 m16-tiles x 4 n8-cols x 4
    float acc[2][4][4];
    #pragma unroll
    for (int i = 0; i < 2; i++)
        #pragma unroll
        for (int j = 0; j < 4; j++)
            #pragma unroll
            for (int q = 0; q < 4; q++) acc[i][j][q] = 0.0f;

    // ldmatrix lane addressing
    const int lm = lane & 15;
    const int lk = lane >> 4;
    int rA[2], rB[2];
    #pragma unroll
    for (int i = 0; i < 2; i++) rA[i] = wm * 32 + i * 16 + lm;
    #pragma unroll
    for (int g = 0; g < 2; g++) rB[g] = wn * 32 + g * 16 + lm;

    // prologue: fill 2 of 3 stages
    load_stage(0, 0);
    if (NK > 1) load_stage(1, 1);

    int buf = 0;
    for (int c = 0; c < NK; c++) {
        if (c < NK - 1) { CP_WAIT1(); } else { CP_WAIT0(); }
        __syncthreads();
        if (c + 2 < NK) {
            int nb = buf + 2; if (nb >= NSTAGE) nb -= NSTAGE;
            load_stage(nb, c + 2);
        }

        const uint32_t stage = sb + buf * STAGE_BYTES;
        #pragma unroll
        for (int ks = 0; ks < 4; ks++) {
            const int atom = ks * 2 + lk;
            uint32_t a0[4], a1[4];
            ldsm_x4(a0, stage + rA[0] * 128 + ((atom ^ (rA[0] & 7)) << 4));
            ldsm_x4(a1, stage + rA[1] * 128 + ((atom ^ (rA[1] & 7)) << 4));
            uint32_t bh[2][4], bl[2][4];
            #pragma unroll
            for (int g = 0; g < 2; g++) {
                ldsm_x4(bh[g], stage + TILE_BYTES + rB[g] * 128 + ((atom ^ (rB[g] & 7)) << 4));
                ldsm_x4(bl[g], stage + 2 * TILE_BYTES + rB[g] * 128 + ((atom ^ (rB[g] & 7)) << 4));
            }
            // pass 0: A·Bh
            #pragma unroll
            for (int g = 0; g < 2; g++) {
                mma_f16(acc[0][2 * g + 0], a0, bh[g][0], bh[g][2]);
                mma_f16(acc[0][2 * g + 1], a0, bh[g][1], bh[g][3]);
                mma_f16(acc[1][2 * g + 0], a1, bh[g][0], bh[g][2]);
                mma_f16(acc[1][2 * g + 1], a1, bh[g][1], bh[g][3]);
            }
            // pass 1: A·Bl
            #pragma unroll
            for (int g = 0; g < 2; g++) {
                mma_f16(acc[0][2 * g + 0], a0, bl[g][0], bl[g][2]);
                mma_f16(acc[0][2 * g + 1], a0, bl[g][1], bl[g][3]);
                mma_f16(acc[1][2 * g + 0], a1, bl[g][0], bl[g][2]);
                mma_f16(acc[1][2 * g + 1], a1, bl[g][1], bl[g][3]);
            }
        }
        buf++; if (buf >= NSTAGE) buf = 0;
    }

    // epilogue: scale + bias
    #pragma unroll
    for (int i = 0; i < 2; i++) {
        #pragma unroll
        for (int half = 0; half < 2; half++) {
            const int row = rowBase + wm * 32 + i * 16 + (lane >> 2) + half * 8;
            const float rb = (biasMode == 2) ? bias[row] : 0.0f;
            #pragma unroll
            for (int j = 0; j < 4; j++) {
                const int col = colBase + wn * 32 + j * 8 + (lane & 3) * 2;
                float v0 = acc[i][j][half * 2 + 0] * scale;
                float v1 = acc[i][j][half * 2 + 1] * scale;
                if (biasMode == 1) { v0 += bias[col]; v1 += bias[col + 1]; }
                else               { v0 += rb;        v1 += rb; }
                const size_t base = (size_t)row * ldc + col;
                if (outMode == 0) {
                    float2 o; o.x = v0; o.y = v1;
                    *(float2*)(Cf + base) = o;
                } else {
                    __half h0 = __float2half_rn(v0);
                    __half h1 = __float2half_rn(v1);
                    __half2 hh; hh.x = h0; hh.y = h1;
                    *(__half2*)(Ch + base) = hh;
                    if (outMode == 2) {
                        __half2 ll;
                        ll.x = __float2half_rn(v0 - __half2float(h0));
                        ll.y = __float2half_rn(v1 - __half2float(h1));
                        *(__half2*)(Cl + base) = ll;
                    }
                }
            }
        }
    }
}

// ---------------------------------------------------------------------------
// split fp32 -> fp16 hi/lo
// ---------------------------------------------------------------------------
__global__ __launch_bounds__(256) void split_f32(
    const float* __restrict__ in, __half* __restrict__ hi,
    __half* __restrict__ lo, size_t n)
{
    size_t i = ((size_t)blockIdx.x * 256 + threadIdx.x) * 4;
    if (i >= n) return;
    float4 v = *(const float4*)(in + i);
    __half h0 = __float2half_rn(v.x), h1 = __float2half_rn(v.y);
    __half h2 = __float2half_rn(v.z), h3 = __float2half_rn(v.w);
    __half2 ha; ha.x = h0; ha.y = h1;
    __half2 hb; hb.x = h2; hb.y = h3;
    __half2 la, lb;
    la.x = __float2half_rn(v.x - __half2float(h0));
    la.y = __float2half_rn(v.y - __half2float(h1));
    lb.x = __float2half_rn(v.z - __half2float(h2));
    lb.y = __float2half_rn(v.w - __half2float(h3));
    *(__half2*)(hi + i) = ha; *(__half2*)(hi + i + 2) = hb;
    *(__half2*)(lo + i) = la; *(__half2*)(lo + i + 2) = lb;
}

// fp32 -> fp16 hi only
__global__ __launch_bounds__(256) void round_f32(
    const float* __restrict__ in, __half* __restrict__ hi, size_t n)
{
    size_t i = ((size_t)blockIdx.x * 256 + threadIdx.x) * 4;
    if (i >= n) return;
    float4 v = *(const float4*)(in + i);
    __half2 ha; ha.x = __float2half_rn(v.x); ha.y = __float2half_rn(v.y);
    __half2 hb; hb.x = __float2half_rn(v.z); hb.y = __float2half_rn(v.w);
    *(__half2*)(hi + i) = ha; *(__half2*)(hi + i + 2) = hb;
}

// ---------------------------------------------------------------------------
// row softmax: fp32 in, fp16 hi out. One block per row of 2048.
// ---------------------------------------------------------------------------
__global__ __launch_bounds__(256) void softmax_h(
    const float* __restrict__ P, __half* __restrict__ Ph, int n)
{
    const float* row = P + (size_t)blockIdx.x * n;
    __half* oh = Ph + (size_t)blockIdx.x * n;
    const int tid = threadIdx.x, lane = tid & 31, wd = tid >> 5;
    __shared__ float red[8];

    float v[8]; float m = -INFINITY;
    #pragma unroll
    for (int i = 0; i < 8; i++) { v[i] = row[tid + i * 256]; m = fmaxf(m, v[i]); }
    #pragma unroll
    for (int o = 16; o > 0; o >>= 1) m = fmaxf(m, __shfl_xor_sync(~0u, m, o));
    if (lane == 0) red[wd] = m;
    __syncthreads();
    float mb = red[0];
    #pragma unroll
    for (int w = 1; w < 8; w++) mb = fmaxf(mb, red[w]);
    __syncthreads();

    float s = 0.0f;
    #pragma unroll
    for (int i = 0; i < 8; i++) { v[i] = __expf(v[i] - mb); s += v[i]; }
    #pragma unroll
    for (int o = 16; o > 0; o >>= 1) s += __shfl_xor_sync(~0u, s, o);
    if (lane == 0) red[wd] = s;
    __syncthreads();
    float sb = 0.0f;
    #pragma unroll
    for (int w = 0; w < 8; w++) sb += red[w];
    const float r = 1.0f / sb;

    #pragma unroll
    for (int i = 0; i < 8; i++)
        oh[tid + i * 256] = __float2half_rn(v[i] * r);
}

// ---------------------------------------------------------------------------
extern "C" void kernel_launch(void* const* d_in, const int* in_sizes, int n_in,
                              void* d_out, int out_size)
{
    (void)in_sizes; (void)n_in; (void)out_size;
    const float* x  = (const float*)d_in[0];
    const float* Wq = (const float*)d_in[1];
    const float* bq = (const float*)d_in[2];
    const float* Wk = (const float*)d_in[3];
    const float* bk = (const float*)d_in[4];
    const float* Wv = (const float*)d_in[5];
    const float* bv = (const float*)d_in[6];
    float* out = (float*)d_out;

    cudaFuncSetAttribute(mma_gemm, cudaFuncAttributeMaxDynamicSharedMemorySize,
                         NSTAGE * STAGE_BYTES);

    __half *xh, *xl, *Wqh, *Wql, *Wkh, *Wkl, *Wvh;
    __half *Qh, *Kh, *Kl, *Vth, *Vtl, *Ph;
    float *P;
    cudaGetSymbolAddress((void**)&xh, g_xh);   cudaGetSymbolAddress((void**)&xl, g_xl);
    cudaGetSymbolAddress((void**)&Wqh, g_Wqh); cudaGetSymbolAddress((void**)&Wql, g_Wql);
    cudaGetSymbolAddress((void**)&Wkh, g_Wkh); cudaGetSymbolAddress((void**)&Wkl, g_Wkl);
    cudaGetSymbolAddress((void**)&Wvh, g_Wvh);
    cudaGetSymbolAddress((void**)&Qh, g_Qh);
    cudaGetSymbolAddress((void**)&Kh, g_KhA);  cudaGetSymbolAddress((void**)&Kl, g_KlA);
    cudaGetSymbolAddress((void**)&Vth, g_Vth); cudaGetSymbolAddress((void**)&Vtl, g_Vtl);
    cudaGetSymbolAddress((void**)&P, g_P);
    cudaGetSymbolAddress((void**)&Ph, g_Ph);

    const size_t nX = (size_t)MTOT * HN;
    const size_t nW = (size_t)HN * HN;
    const int smem = NSTAGE * STAGE_BYTES;

    // 0) split/round inputs to fp16
    split_f32<<<(unsigned)(nX / 4 / 256), 256>>>(x,  xh,  xl,  nX);
    split_f32<<<(unsigned)(nW / 4 / 256), 256>>>(Wq, Wqh, Wql, nW);
    split_f32<<<(unsigned)(nW / 4 / 256), 256>>>(Wk, Wkh, Wkl, nW);
    round_f32<<<(unsigned)(nW / 4 / 256), 256>>>(Wv, Wvh, nW);

    // 1) Q = xh @ (Wqh+Wql)^T + bq -> Qh (hi only);  K -> Kh,Kl (split)
    {
        dim3 g(HN / 128, MTOT / 128, 1);
        mma_gemm<<<g, 512, smem>>>(xh, Wqh, Wql, bq, 1, 1.0f,
                                   nullptr, Qh, nullptr, 1, HN, HN, 0, 0, 0);
        mma_gemm<<<g, 512, smem>>>(xh, Wkh, Wkl, bk, 1, 1.0f,
                                   nullptr, Kh, Kl, 2, HN, HN, 0, 0, 0);
    }
    // 2) Vt_b = Wvh @ (xh+xl)_b^T + bv[row] -> Vth,Vtl (split)
    {
        dim3 g(SN / 128, HN / 128, BN);
        mma_gemm<<<g, 512, smem>>>(Wvh, xh, xl, bv, 2, 1.0f,
                                   nullptr, Vth, Vtl, 2, HN, SN,
                                   0, (size_t)SN * HN, (size_t)HN * SN);
    }
    // 3) scores = Qh_b @ (Kh+Kl)_b^T / 32 -> fp32 P
    {
        dim3 g(SN / 128, SN / 128, BN);
        mma_gemm<<<g, 512, smem>>>(Qh, Kh, Kl, nullptr, 0, 0.03125f,
                                   P, nullptr, nullptr, 0, HN, SN,
                                   (size_t)SN * HN, (size_t)SN * HN, (size_t)SN * SN);
    }
    // 4) softmax rows -> Ph (hi only)
    softmax_h<<<BN * SN, 256>>>(P, Ph, SN);

    // 5) out = Ph_b @ (Vth+Vtl)_b^T -> fp32
    {
        dim3 g(HN / 128, SN / 128, BN);
        mma_gemm<<<g, 512, smem>>>(Ph, Vth, Vtl, nullptr, 0, 1.0f,
                                   out, nullptr, nullptr, 0, SN, HN,
                                   (size_t)SN * SN, (size_t)HN * SN, (size_t)SN * HN);
    }
}

// round 10
// speedup vs baseline: 4.3037x; 1.0337x over previous
#include <cuda_runtime.h>
#include <cuda_fp16.h>
#include <math.h>
#include <stdint.h>

#define BN 4
#define SN 2048
#define HN 1024
#define MTOT (BN * SN)

// ---------------------------------------------------------------------------
// Scratch (__device__ globals; allocation-free rule)
// ---------------------------------------------------------------------------
__device__ __half g_xh[(size_t)MTOT * HN], g_xl[(size_t)MTOT * HN];
__device__ __half g_Wqh[(size_t)HN * HN], g_Wql[(size_t)HN * HN];
__device__ __half g_Wkh[(size_t)HN * HN], g_Wkl[(size_t)HN * HN];
__device__ __half g_Wvh[(size_t)HN * HN];
__device__ __half g_Qh[(size_t)MTOT * HN];
__device__ __half g_KhA[(size_t)MTOT * HN], g_KlA[(size_t)MTOT * HN];
__device__ __half g_Vth[(size_t)BN * HN * SN], g_Vtl[(size_t)BN * HN * SN];
__device__ float  g_P[(size_t)BN * SN * SN];
__device__ __half g_Ph[(size_t)BN * SN * SN];

// ---------------------------------------------------------------------------
// Helpers (compute_103-safe: ldmatrix + mma.sync + cp.async only)
// ---------------------------------------------------------------------------
__device__ __forceinline__ uint32_t smem_u32(const void* p) {
    uint32_t a;
    asm("{ .reg .u64 t; cvta.to.shared.u64 t, %1; cvt.u32.u64 %0, t; }" : "=r"(a) : "l"(p));
    return a;
}
__device__ __forceinline__ void ldsm_x4(uint32_t* r, uint32_t a) {
    asm volatile("ldmatrix.sync.aligned.m8n8.x4.shared.b16 {%0,%1,%2,%3}, [%4];"
                 : "=r"(r[0]), "=r"(r[1]), "=r"(r[2]), "=r"(r[3]) : "r"(a));
}
__device__ __forceinline__ void mma_f16(float* c, const uint32_t* a,
                                        uint32_t b0, uint32_t b1) {
    asm volatile("mma.sync.aligned.m16n8k16.row.col.f32.f16.f16.f32 "
                 "{%0,%1,%2,%3}, {%4,%5,%6,%7}, {%8,%9}, {%0,%1,%2,%3};"
                 : "+f"(c[0]), "+f"(c[1]), "+f"(c[2]), "+f"(c[3])
                 : "r"(a[0]), "r"(a[1]), "r"(a[2]), "r"(a[3]), "r"(b0), "r"(b1));
}
#define CP_COMMIT() asm volatile("cp.async.commit_group;" ::: "memory")
#define CP_WAIT1()  asm volatile("cp.async.wait_group 1;" ::: "memory")
#define CP_WAIT0()  asm volatile("cp.async.wait_group 0;" ::: "memory")

// ---------------------------------------------------------------------------
// NT GEMM via mma.sync fp16, 2-pass split-B:
//   C[M,N] = scale * sum_k A[m,k]*(Bh+Bl)[n,k] + bias
// Tile 256x128 (tall M to balance cp.async-issue vs HMMA), BK=64
// (128B rows, SW128 xor swizzle), 512 threads, warp grid 4(m)x4(n),
// warp tile 64x32. 3-stage cp.async pipeline.
// biasMode: 0 none, 1 bias[col], 2 bias[row].
// outMode: 0 fp32, 1 fp16 hi only, 2 fp16 hi+lo.
// Requires M%256==0, N%128==0, K%64==0.
// ---------------------------------------------------------------------------
#define A_BYTES     32768              // 256 rows x 128B
#define B_BYTES     16384              // 128 rows x 128B
#define STAGE_BYTES (A_BYTES + 2 * B_BYTES)   // 64 KB
#define NSTAGE      3

__global__ __launch_bounds__(512, 1)
void mma_gemm(const __half* __restrict__ A, const __half* __restrict__ Bh,
              const __half* __restrict__ Bl,
              const float* __restrict__ bias, int biasMode, float scale,
              float* __restrict__ Cf, __half* __restrict__ Ch,
              __half* __restrict__ Cl, int outMode, int K, int ldc,
              size_t szA, size_t szB, size_t szC)
{
    extern __shared__ char smem[];
    const uint32_t sb = smem_u32(smem);
    const int tid = threadIdx.x, lane = tid & 31, wid = tid >> 5;
    const int wm = wid & 3, wn = wid >> 2;   // 4 x 4 warp grid, warp tile 64x32

    A  += (size_t)blockIdx.z * szA;
    Bh += (size_t)blockIdx.z * szB;  Bl += (size_t)blockIdx.z * szB;
    if (outMode == 0) Cf += (size_t)blockIdx.z * szC;
    else { Ch += (size_t)blockIdx.z * szC; if (outMode == 2) Cl += (size_t)blockIdx.z * szC; }

    const int rowBase = blockIdx.y * 256;
    const int colBase = blockIdx.x * 128;

    const __half* tA  = A  + (size_t)rowBase * K;
    const __half* tBh = Bh + (size_t)colBase * K;
    const __half* tBl = Bl + (size_t)colBase * K;

    const int NK = K >> 6;

    // stage loaders: 16B cp.async, SW128 swizzle
    auto load_A = [&](uint32_t dst, const __half* g) {
        #pragma unroll
        for (int i = 0; i < 4; i++) {               // 2048 ops / 512 thr
            int idx = i * 512 + tid;
            int row = idx >> 3;
            int kb  = idx & 7;
            uint32_t off = row * 128 + kb * 16;
            uint32_t sw  = off ^ ((off >> 3) & 0x70);
            const void* src = (const void*)(g + (size_t)row * K + kb * 8);
            asm volatile("cp.async.cg.shared.global [%0], [%1], 16;"
                         :: "r"(dst + sw), "l"(src));
        }
    };
    auto load_B = [&](uint32_t dst, const __half* g) {
        #pragma unroll
        for (int i = 0; i < 2; i++) {               // 1024 ops / 512 thr
            int idx = i * 512 + tid;
            int row = idx >> 3;
            int kb  = idx & 7;
            uint32_t off = row * 128 + kb * 16;
            uint32_t sw  = off ^ ((off >> 3) & 0x70);
            const void* src = (const void*)(g + (size_t)row * K + kb * 8);
            asm volatile("cp.async.cg.shared.global [%0], [%1], 16;"
                         :: "r"(dst + sw), "l"(src));
        }
    };
    auto load_stage = [&](int buf, int c) {
        uint32_t st = sb + buf * STAGE_BYTES;
        size_t ko = (size_t)c * 64;
        load_A(st,                    tA  + ko);
        load_B(st + A_BYTES,          tBh + ko);
        load_B(st + A_BYTES + B_BYTES, tBl + ko);
        CP_COMMIT();
    };

    // accumulators: 4 m16-tiles x 4 n8-cols x 4 = 64 fp32
    float acc[4][4][4];
    #pragma unroll
    for (int i = 0; i < 4; i++)
        #pragma unroll
        for (int j = 0; j < 4; j++)
            #pragma unroll
            for (int q = 0; q < 4; q++) acc[i][j][q] = 0.0f;

    // ldmatrix lane addressing
    const int lm = lane & 15;
    const int lk = lane >> 4;
    int rA[4], rB[2];
    #pragma unroll
    for (int i = 0; i < 4; i++) rA[i] = wm * 64 + i * 16 + lm;
    #pragma unroll
    for (int g = 0; g < 2; g++) rB[g] = wn * 32 + g * 16 + lm;

    // prologue: fill 2 of 3 stages
    load_stage(0, 0);
    if (NK > 1) load_stage(1, 1);

    int buf = 0;
    for (int c = 0; c < NK; c++) {
        if (c < NK - 1) { CP_WAIT1(); } else { CP_WAIT0(); }
        __syncthreads();
        if (c + 2 < NK) {
            int nb = buf + 2; if (nb >= NSTAGE) nb -= NSTAGE;
            load_stage(nb, c + 2);
        }

        const uint32_t stage = sb + buf * STAGE_BYTES;
        #pragma unroll
        for (int ks = 0; ks < 4; ks++) {
            const int atom = ks * 2 + lk;
            uint32_t a[4][4];
            #pragma unroll
            for (int i = 0; i < 4; i++)
                ldsm_x4(a[i], stage + rA[i] * 128 + ((atom ^ (rA[i] & 7)) << 4));
            uint32_t bh[2][4], bl[2][4];
            #pragma unroll
            for (int g = 0; g < 2; g++) {
                ldsm_x4(bh[g], stage + A_BYTES + rB[g] * 128 + ((atom ^ (rB[g] & 7)) << 4));
                ldsm_x4(bl[g], stage + A_BYTES + B_BYTES + rB[g] * 128 + ((atom ^ (rB[g] & 7)) << 4));
            }
            // pass 0: A·Bh
            #pragma unroll
            for (int i = 0; i < 4; i++)
                #pragma unroll
                for (int g = 0; g < 2; g++) {
                    mma_f16(acc[i][2 * g + 0], a[i], bh[g][0], bh[g][2]);
                    mma_f16(acc[i][2 * g + 1], a[i], bh[g][1], bh[g][3]);
                }
            // pass 1: A·Bl
            #pragma unroll
            for (int i = 0; i < 4; i++)
                #pragma unroll
                for (int g = 0; g < 2; g++) {
                    mma_f16(acc[i][2 * g + 0], a[i], bl[g][0], bl[g][2]);
                    mma_f16(acc[i][2 * g + 1], a[i], bl[g][1], bl[g][3]);
                }
        }
        buf++; if (buf >= NSTAGE) buf = 0;
    }

    // epilogue: scale + bias
    #pragma unroll
    for (int i = 0; i < 4; i++) {
        #pragma unroll
        for (int half = 0; half < 2; half++) {
            const int row = rowBase + wm * 64 + i * 16 + (lane >> 2) + half * 8;
            const float rb = (biasMode == 2) ? bias[row] : 0.0f;
            #pragma unroll
            for (int j = 0; j < 4; j++) {
                const int col = colBase + wn * 32 + j * 8 + (lane & 3) * 2;
                float v0 = acc[i][j][half * 2 + 0] * scale;
                float v1 = acc[i][j][half * 2 + 1] * scale;
                if (biasMode == 1) { v0 += bias[col]; v1 += bias[col + 1]; }
                else               { v0 += rb;        v1 += rb; }
                const size_t base = (size_t)row * ldc + col;
                if (outMode == 0) {
                    float2 o; o.x = v0; o.y = v1;
                    *(float2*)(Cf + base) = o;
                } else {
                    __half h0 = __float2half_rn(v0);
                    __half h1 = __float2half_rn(v1);
                    __half2 hh; hh.x = h0; hh.y = h1;
                    *(__half2*)(Ch + base) = hh;
                    if (outMode == 2) {
                        __half2 ll;
                        ll.x = __float2half_rn(v0 - __half2float(h0));
                        ll.y = __float2half_rn(v1 - __half2float(h1));
                        *(__half2*)(Cl + base) = ll;
                    }
                }
            }
        }
    }
}

// ---------------------------------------------------------------------------
// split fp32 -> fp16 hi/lo
// ---------------------------------------------------------------------------
__global__ __launch_bounds__(256) void split_f32(
    const float* __restrict__ in, __half* __restrict__ hi,
    __half* __restrict__ lo, size_t n)
{
    size_t i = ((size_t)blockIdx.x * 256 + threadIdx.x) * 4;
    if (i >= n) return;
    float4 v = *(const float4*)(in + i);
    __half h0 = __float2half_rn(v.x), h1 = __float2half_rn(v.y);
    __half h2 = __float2half_rn(v.z), h3 = __float2half_rn(v.w);
    __half2 ha; ha.x = h0; ha.y = h1;
    __half2 hb; hb.x = h2; hb.y = h3;
    __half2 la, lb;
    la.x = __float2half_rn(v.x - __half2float(h0));
    la.y = __float2half_rn(v.y - __half2float(h1));
    lb.x = __float2half_rn(v.z - __half2float(h2));
    lb.y = __float2half_rn(v.w - __half2float(h3));
    *(__half2*)(hi + i) = ha; *(__half2*)(hi + i + 2) = hb;
    *(__half2*)(lo + i) = la; *(__half2*)(lo + i + 2) = lb;
}

// fp32 -> fp16 hi only
__global__ __launch_bounds__(256) void round_f32(
    const float* __restrict__ in, __half* __restrict__ hi, size_t n)
{
    size_t i = ((size_t)blockIdx.x * 256 + threadIdx.x) * 4;
    if (i >= n) return;
    float4 v = *(const float4*)(in + i);
    __half2 ha; ha.x = __float2half_rn(v.x); ha.y = __float2half_rn(v.y);
    __half2 hb; hb.x = __float2half_rn(v.z); hb.y = __float2half_rn(v.w);
    *(__half2*)(hi + i) = ha; *(__half2*)(hi + i + 2) = hb;
}

// ---------------------------------------------------------------------------
// row softmax: fp32 in, fp16 hi out. One block per row of 2048.
// ---------------------------------------------------------------------------
__global__ __launch_bounds__(256) void softmax_h(
    const float* __restrict__ P, __half* __restrict__ Ph, int n)
{
    const float* row = P + (size_t)blockIdx.x * n;
    __half* oh = Ph + (size_t)blockIdx.x * n;
    const int tid = threadIdx.x, lane = tid & 31, wd = tid >> 5;
    __shared__ float red[8];

    float v[8]; float m = -INFINITY;
    #pragma unroll
    for (int i = 0; i < 8; i++) { v[i] = row[tid + i * 256]; m = fmaxf(m, v[i]); }
    #pragma unroll
    for (int o = 16; o > 0; o >>= 1) m = fmaxf(m, __shfl_xor_sync(~0u, m, o));
    if (lane == 0) red[wd] = m;
    __syncthreads();
    float mb = red[0];
    #pragma unroll
    for (int w = 1; w < 8; w++) mb = fmaxf(mb, red[w]);
    __syncthreads();

    float s = 0.0f;
    #pragma unroll
    for (int i = 0; i < 8; i++) { v[i] = __expf(v[i] - mb); s += v[i]; }
    #pragma unroll
    for (int o = 16; o > 0; o >>= 1) s += __shfl_xor_sync(~0u, s, o);
    if (lane == 0) red[wd] = s;
    __syncthreads();
    float sb = 0.0f;
    #pragma unroll
    for (int w = 0; w < 8; w++) sb += red[w];
    const float r = 1.0f / sb;

    #pragma unroll
    for (int i = 0; i < 8; i++)
        oh[tid + i * 256] = __float2half_rn(v[i] * r);
}

// ---------------------------------------------------------------------------
extern "C" void kernel_launch(void* const* d_in, const int* in_sizes, int n_in,
                              void* d_out, int out_size)
{
    (void)in_sizes; (void)n_in; (void)out_size;
    const float* x  = (const float*)d_in[0];
    const float* Wq = (const float*)d_in[1];
    const float* bq = (const float*)d_in[2];
    const float* Wk = (const float*)d_in[3];
    const float* bk = (const float*)d_in[4];
    const float* Wv = (const float*)d_in[5];
    const float* bv = (const float*)d_in[6];
    float* out = (float*)d_out;

    cudaFuncSetAttribute(mma_gemm, cudaFuncAttributeMaxDynamicSharedMemorySize,
                         NSTAGE * STAGE_BYTES);

    __half *xh, *xl, *Wqh, *Wql, *Wkh, *Wkl, *Wvh;
    __half *Qh, *Kh, *Kl, *Vth, *Vtl, *Ph;
    float *P;
    cudaGetSymbolAddress((void**)&xh, g_xh);   cudaGetSymbolAddress((void**)&xl, g_xl);
    cudaGetSymbolAddress((void**)&Wqh, g_Wqh); cudaGetSymbolAddress((void**)&Wql, g_Wql);
    cudaGetSymbolAddress((void**)&Wkh, g_Wkh); cudaGetSymbolAddress((void**)&Wkl, g_Wkl);
    cudaGetSymbolAddress((void**)&Wvh, g_Wvh);
    cudaGetSymbolAddress((void**)&Qh, g_Qh);
    cudaGetSymbolAddress((void**)&Kh, g_KhA);  cudaGetSymbolAddress((void**)&Kl, g_KlA);
    cudaGetSymbolAddress((void**)&Vth, g_Vth); cudaGetSymbolAddress((void**)&Vtl, g_Vtl);
    cudaGetSymbolAddress((void**)&P, g_P);
    cudaGetSymbolAddress((void**)&Ph, g_Ph);

    const size_t nX = (size_t)MTOT * HN;
    const size_t nW = (size_t)HN * HN;
    const int smem = NSTAGE * STAGE_BYTES;

    // 0) split/round inputs to fp16
    split_f32<<<(unsigned)(nX / 4 / 256), 256>>>(x,  xh,  xl,  nX);
    split_f32<<<(unsigned)(nW / 4 / 256), 256>>>(Wq, Wqh, Wql, nW);
    split_f32<<<(unsigned)(nW / 4 / 256), 256>>>(Wk, Wkh, Wkl, nW);
    round_f32<<<(unsigned)(nW / 4 / 256), 256>>>(Wv, Wvh, nW);

    // 1) Q = xh @ (Wqh+Wql)^T + bq -> Qh (hi only);  K -> Kh,Kl (split)
    {
        dim3 g(HN / 128, MTOT / 256, 1);
        mma_gemm<<<g, 512, smem>>>(xh, Wqh, Wql, bq, 1, 1.0f,
                                   nullptr, Qh, nullptr, 1, HN, HN, 0, 0, 0);
        mma_gemm<<<g, 512, smem>>>(xh, Wkh, Wkl, bk, 1, 1.0f,
                                   nullptr, Kh, Kl, 2, HN, HN, 0, 0, 0);
    }
    // 2) Vt_b = Wvh @ (xh+xl)_b^T + bv[row] -> Vth,Vtl (split)
    {
        dim3 g(SN / 128, HN / 256, BN);
        mma_gemm<<<g, 512, smem>>>(Wvh, xh, xl, bv, 2, 1.0f,
                                   nullptr, Vth, Vtl, 2, HN, SN,
                                   0, (size_t)SN * HN, (size_t)HN * SN);
    }
    // 3) scores = Qh_b @ (Kh+Kl)_b^T / 32 -> fp32 P
    {
        dim3 g(SN / 128, SN / 256, BN);
        mma_gemm<<<g, 512, smem>>>(Qh, Kh, Kl, nullptr, 0, 0.03125f,
                                   P, nullptr, nullptr, 0, HN, SN,
                                   (size_t)SN * HN, (size_t)SN * HN, (size_t)SN * SN);
    }
    // 4) softmax rows -> Ph (hi only)
    softmax_h<<<BN * SN, 256>>>(P, Ph, SN);

    // 5) out = Ph_b @ (Vth+Vtl)_b^T -> fp32
    {
        dim3 g(HN / 128, SN / 256, BN);
        mma_gemm<<<g, 512, smem>>>(Ph, Vth, Vtl, nullptr, 0, 1.0f,
                                   out, nullptr, nullptr, 0, SN, HN,
                                   (size_t)SN * SN, (size_t)HN * SN, (size_t)SN * HN);
    }
}

// round 11
// speedup vs baseline: 5.7256x; 1.3304x over previous
#include <cuda_runtime.h>
#include <cuda_fp16.h>
#include <math.h>
#include <stdint.h>

#define BN 4
#define SN 2048
#define HN 1024
#define MTOT (BN * SN)

// ---------------------------------------------------------------------------
// Scratch (__device__ globals; allocation-free rule)
// ---------------------------------------------------------------------------
__device__ __half g_xh[(size_t)MTOT * HN], g_xl[(size_t)MTOT * HN];
__device__ __half g_Wqh[(size_t)HN * HN], g_Wql[(size_t)HN * HN];
__device__ __half g_Wkh[(size_t)HN * HN], g_Wkl[(size_t)HN * HN];
__device__ __half g_Wvh[(size_t)HN * HN];
__device__ __half g_Qh[(size_t)MTOT * HN];
__device__ __half g_KhA[(size_t)MTOT * HN];
__device__ __half g_Vth[(size_t)BN * HN * SN];
__device__ float  g_P[(size_t)BN * SN * SN];
__device__ __half g_Ph[(size_t)BN * SN * SN];

// ---------------------------------------------------------------------------
// Helpers (compute_103-safe: ldmatrix + mma.sync + cp.async only)
// ---------------------------------------------------------------------------
__device__ __forceinline__ uint32_t smem_u32(const void* p) {
    uint32_t a;
    asm("{ .reg .u64 t; cvta.to.shared.u64 t, %1; cvt.u32.u64 %0, t; }" : "=r"(a) : "l"(p));
    return a;
}
__device__ __forceinline__ void ldsm_x4(uint32_t* r, uint32_t a) {
    asm volatile("ldmatrix.sync.aligned.m8n8.x4.shared.b16 {%0,%1,%2,%3}, [%4];"
                 : "=r"(r[0]), "=r"(r[1]), "=r"(r[2]), "=r"(r[3]) : "r"(a));
}
__device__ __forceinline__ void mma_f16(float* c, const uint32_t* a,
                                        uint32_t b0, uint32_t b1) {
    asm volatile("mma.sync.aligned.m16n8k16.row.col.f32.f16.f16.f32 "
                 "{%0,%1,%2,%3}, {%4,%5,%6,%7}, {%8,%9}, {%0,%1,%2,%3};"
                 : "+f"(c[0]), "+f"(c[1]), "+f"(c[2]), "+f"(c[3])
                 : "r"(a[0]), "r"(a[1]), "r"(a[2]), "r"(a[3]), "r"(b0), "r"(b1));
}
#define CP_COMMIT() asm volatile("cp.async.commit_group;" ::: "memory")
#define CP_WAIT1()  asm volatile("cp.async.wait_group 1;" ::: "memory")
#define CP_WAIT0()  asm volatile("cp.async.wait_group 0;" ::: "memory")

// ---------------------------------------------------------------------------
// NT GEMM via mma.sync fp16:
//   npass=2: C = scale * sum_k A[m,k]*(Bh+Bl)[n,k] + bias   (split-B)
//   npass=1: C = scale * sum_k A[m,k]*Bh[n,k] + bias        (plain fp16)
// Tile 256x128, BK=64 (128B rows, SW128 xor swizzle), 512 threads,
// warp grid 4(m)x4(n), warp tile 64x32. 3-stage cp.async pipeline.
// biasMode: 0 none, 1 bias[col], 2 bias[row].
// outMode: 0 fp32, 1 fp16 hi only.
// Requires M%256==0, N%128==0, K%64==0.
// ---------------------------------------------------------------------------
#define A_BYTES 32768              // 256 rows x 128B
#define B_BYTES 16384              // 128 rows x 128B
#define NSTAGE  3

__global__ __launch_bounds__(512, 1)
void mma_gemm(const __half* __restrict__ A, const __half* __restrict__ Bh,
              const __half* __restrict__ Bl, int npass,
              const float* __restrict__ bias, int biasMode, float scale,
              float* __restrict__ Cf, __half* __restrict__ Ch,
              int outMode, int K, int ldc,
              size_t szA, size_t szB, size_t szC)
{
    extern __shared__ char smem[];
    const uint32_t sb = smem_u32(smem);
    const int tid = threadIdx.x, lane = tid & 31, wid = tid >> 5;
    const int wm = wid & 3, wn = wid >> 2;   // 4 x 4 warp grid, warp tile 64x32
    const uint32_t stageBytes = A_BYTES + (npass == 2 ? 2 : 1) * B_BYTES;

    A  += (size_t)blockIdx.z * szA;
    Bh += (size_t)blockIdx.z * szB;
    if (npass == 2) Bl += (size_t)blockIdx.z * szB;
    if (outMode == 0) Cf += (size_t)blockIdx.z * szC;
    else              Ch += (size_t)blockIdx.z * szC;

    const int rowBase = blockIdx.y * 256;
    const int colBase = blockIdx.x * 128;

    const __half* tA  = A  + (size_t)rowBase * K;
    const __half* tBh = Bh + (size_t)colBase * K;
    const __half* tBl = (npass == 2) ? (Bl + (size_t)colBase * K) : tBh;

    const int NK = K >> 6;

    // stage loaders: 16B cp.async, SW128 swizzle
    auto load_A = [&](uint32_t dst, const __half* g) {
        #pragma unroll
        for (int i = 0; i < 4; i++) {
            int idx = i * 512 + tid;
            int row = idx >> 3;
            int kb  = idx & 7;
            uint32_t off = row * 128 + kb * 16;
            uint32_t sw  = off ^ ((off >> 3) & 0x70);
            const void* src = (const void*)(g + (size_t)row * K + kb * 8);
            asm volatile("cp.async.cg.shared.global [%0], [%1], 16;"
                         :: "r"(dst + sw), "l"(src));
        }
    };
    auto load_B = [&](uint32_t dst, const __half* g) {
        #pragma unroll
        for (int i = 0; i < 2; i++) {
            int idx = i * 512 + tid;
            int row = idx >> 3;
            int kb  = idx & 7;
            uint32_t off = row * 128 + kb * 16;
            uint32_t sw  = off ^ ((off >> 3) & 0x70);
            const void* src = (const void*)(g + (size_t)row * K + kb * 8);
            asm volatile("cp.async.cg.shared.global [%0], [%1], 16;"
                         :: "r"(dst + sw), "l"(src));
        }
    };
    auto load_stage = [&](int buf, int c) {
        uint32_t st = sb + buf * stageBytes;
        size_t ko = (size_t)c * 64;
        load_A(st, tA + ko);
        load_B(st + A_BYTES, tBh + ko);
        if (npass == 2) load_B(st + A_BYTES + B_BYTES, tBl + ko);
        CP_COMMIT();
    };

    // accumulators: 4 m16-tiles x 4 n8-cols x 4 = 64 fp32
    float acc[4][4][4];
    #pragma unroll
    for (int i = 0; i < 4; i++)
        #pragma unroll
        for (int j = 0; j < 4; j++)
            #pragma unroll
            for (int q = 0; q < 4; q++) acc[i][j][q] = 0.0f;

    // ldmatrix lane addressing
    const int lm = lane & 15;
    const int lk = lane >> 4;
    int rA[4], rB[2];
    #pragma unroll
    for (int i = 0; i < 4; i++) rA[i] = wm * 64 + i * 16 + lm;
    #pragma unroll
    for (int g = 0; g < 2; g++) rB[g] = wn * 32 + g * 16 + lm;

    // prologue: fill 2 of 3 stages
    load_stage(0, 0);
    if (NK > 1) load_stage(1, 1);

    int buf = 0;
    for (int c = 0; c < NK; c++) {
        if (c < NK - 1) { CP_WAIT1(); } else { CP_WAIT0(); }
        __syncthreads();
        if (c + 2 < NK) {
            int nb = buf + 2; if (nb >= NSTAGE) nb -= NSTAGE;
            load_stage(nb, c + 2);
        }

        const uint32_t stage = sb + buf * stageBytes;
        #pragma unroll
        for (int ks = 0; ks < 4; ks++) {
            const int atom = ks * 2 + lk;
            uint32_t a[4][4];
            #pragma unroll
            for (int i = 0; i < 4; i++)
                ldsm_x4(a[i], stage + rA[i] * 128 + ((atom ^ (rA[i] & 7)) << 4));
            uint32_t bh[2][4];
            #pragma unroll
            for (int g = 0; g < 2; g++)
                ldsm_x4(bh[g], stage + A_BYTES + rB[g] * 128 + ((atom ^ (rB[g] & 7)) << 4));
            // pass 0: A·Bh
            #pragma unroll
            for (int i = 0; i < 4; i++)
                #pragma unroll
                for (int g = 0; g < 2; g++) {
                    mma_f16(acc[i][2 * g + 0], a[i], bh[g][0], bh[g][2]);
                    mma_f16(acc[i][2 * g + 1], a[i], bh[g][1], bh[g][3]);
                }
            // pass 1: A·Bl (split-B only)
            if (npass == 2) {
                uint32_t bl[2][4];
                #pragma unroll
                for (int g = 0; g < 2; g++)
                    ldsm_x4(bl[g], stage + A_BYTES + B_BYTES + rB[g] * 128 + ((atom ^ (rB[g] & 7)) << 4));
                #pragma unroll
                for (int i = 0; i < 4; i++)
                    #pragma unroll
                    for (int g = 0; g < 2; g++) {
                        mma_f16(acc[i][2 * g + 0], a[i], bl[g][0], bl[g][2]);
                        mma_f16(acc[i][2 * g + 1], a[i], bl[g][1], bl[g][3]);
                    }
            }
        }
        buf++; if (buf >= NSTAGE) buf = 0;
    }

    // epilogue: scale + bias
    #pragma unroll
    for (int i = 0; i < 4; i++) {
        #pragma unroll
        for (int half = 0; half < 2; half++) {
            const int row = rowBase + wm * 64 + i * 16 + (lane >> 2) + half * 8;
            const float rb = (biasMode == 2) ? bias[row] : 0.0f;
            #pragma unroll
            for (int j = 0; j < 4; j++) {
                const int col = colBase + wn * 32 + j * 8 + (lane & 3) * 2;
                float v0 = acc[i][j][half * 2 + 0] * scale;
                float v1 = acc[i][j][half * 2 + 1] * scale;
                if (biasMode == 1) { v0 += bias[col]; v1 += bias[col + 1]; }
                else               { v0 += rb;        v1 += rb; }
                const size_t base = (size_t)row * ldc + col;
                if (outMode == 0) {
                    float2 o; o.x = v0; o.y = v1;
                    *(float2*)(Cf + base) = o;
                } else {
                    __half2 hh; hh.x = __float2half_rn(v0); hh.y = __float2half_rn(v1);
                    *(__half2*)(Ch + base) = hh;
                }
            }
        }
    }
}

// ---------------------------------------------------------------------------
// split fp32 -> fp16 hi/lo
// ---------------------------------------------------------------------------
__global__ __launch_bounds__(256) void split_f32(
    const float* __restrict__ in, __half* __restrict__ hi,
    __half* __restrict__ lo, size_t n)
{
    size_t i = ((size_t)blockIdx.x * 256 + threadIdx.x) * 4;
    if (i >= n) return;
    float4 v = *(const float4*)(in + i);
    __half h0 = __float2half_rn(v.x), h1 = __float2half_rn(v.y);
    __half h2 = __float2half_rn(v.z), h3 = __float2half_rn(v.w);
    __half2 ha; ha.x = h0; ha.y = h1;
    __half2 hb; hb.x = h2; hb.y = h3;
    __half2 la, lb;
    la.x = __float2half_rn(v.x - __half2float(h0));
    la.y = __float2half_rn(v.y - __half2float(h1));
    lb.x = __float2half_rn(v.z - __half2float(h2));
    lb.y = __float2half_rn(v.w - __half2float(h3));
    *(__half2*)(hi + i) = ha; *(__half2*)(hi + i + 2) = hb;
    *(__half2*)(lo + i) = la; *(__half2*)(lo + i + 2) = lb;
}

// fp32 -> fp16 hi only
__global__ __launch_bounds__(256) void round_f32(
    const float* __restrict__ in, __half* __restrict__ hi, size_t n)
{
    size_t i = ((size_t)blockIdx.x * 256 + threadIdx.x) * 4;
    if (i >= n) return;
    float4 v = *(const float4*)(in + i);
    __half2 ha; ha.x = __float2half_rn(v.x); ha.y = __float2half_rn(v.y);
    __half2 hb; hb.x = __float2half_rn(v.z); hb.y = __float2half_rn(v.w);
    *(__half2*)(hi + i) = ha; *(__half2*)(hi + i + 2) = hb;
}

// ---------------------------------------------------------------------------
// row softmax: fp32 in, fp16 hi out. One block per row of 2048.
// ---------------------------------------------------------------------------
__global__ __launch_bounds__(256) void softmax_h(
    const float* __restrict__ P, __half* __restrict__ Ph, int n)
{
    const float* row = P + (size_t)blockIdx.x * n;
    __half* oh = Ph + (size_t)blockIdx.x * n;
    const int tid = threadIdx.x, lane = tid & 31, wd = tid >> 5;
    __shared__ float red[8];

    float v[8]; float m = -INFINITY;
    #pragma unroll
    for (int i = 0; i < 8; i++) { v[i] = row[tid + i * 256]; m = fmaxf(m, v[i]); }
    #pragma unroll
    for (int o = 16; o > 0; o >>= 1) m = fmaxf(m, __shfl_xor_sync(~0u, m, o));
    if (lane == 0) red[wd] = m;
    __syncthreads();
    float mb = red[0];
    #pragma unroll
    for (int w = 1; w < 8; w++) mb = fmaxf(mb, red[w]);
    __syncthreads();

    float s = 0.0f;
    #pragma unroll
    for (int i = 0; i < 8; i++) { v[i] = __expf(v[i] - mb); s += v[i]; }
    #pragma unroll
    for (int o = 16; o > 0; o >>= 1) s += __shfl_xor_sync(~0u, s, o);
    if (lane == 0) red[wd] = s;
    __syncthreads();
    float sb = 0.0f;
    #pragma unroll
    for (int w = 0; w < 8; w++) sb += red[w];
    const float r = 1.0f / sb;

    #pragma unroll
    for (int i = 0; i < 8; i++)
        oh[tid + i * 256] = __float2half_rn(v[i] * r);
}

// ---------------------------------------------------------------------------
extern "C" void kernel_launch(void* const* d_in, const int* in_sizes, int n_in,
                              void* d_out, int out_size)
{
    (void)in_sizes; (void)n_in; (void)out_size;
    const float* x  = (const float*)d_in[0];
    const float* Wq = (const float*)d_in[1];
    const float* bq = (const float*)d_in[2];
    const float* Wk = (const float*)d_in[3];
    const float* bk = (const float*)d_in[4];
    const float* Wv = (const float*)d_in[5];
    const float* bv = (const float*)d_in[6];
    float* out = (float*)d_out;

    const int smem2 = NSTAGE * (A_BYTES + 2 * B_BYTES);   // 192 KB (2-pass)
    const int smem1 = NSTAGE * (A_BYTES + B_BYTES);       // 144 KB (1-pass)
    cudaFuncSetAttribute(mma_gemm, cudaFuncAttributeMaxDynamicSharedMemorySize, smem2);

    __half *xh, *xl, *Wqh, *Wql, *Wkh, *Wkl, *Wvh;
    __half *Qh, *Kh, *Vth, *Ph;
    float *P;
    cudaGetSymbolAddress((void**)&xh, g_xh);   cudaGetSymbolAddress((void**)&xl, g_xl);
    cudaGetSymbolAddress((void**)&Wqh, g_Wqh); cudaGetSymbolAddress((void**)&Wql, g_Wql);
    cudaGetSymbolAddress((void**)&Wkh, g_Wkh); cudaGetSymbolAddress((void**)&Wkl, g_Wkl);
    cudaGetSymbolAddress((void**)&Wvh, g_Wvh);
    cudaGetSymbolAddress((void**)&Qh, g_Qh);
    cudaGetSymbolAddress((void**)&Kh, g_KhA);
    cudaGetSymbolAddress((void**)&Vth, g_Vth);
    cudaGetSymbolAddress((void**)&P, g_P);
    cudaGetSymbolAddress((void**)&Ph, g_Ph);

    const size_t nX = (size_t)MTOT * HN;
    const size_t nW = (size_t)HN * HN;

    // 0) split/round inputs to fp16
    split_f32<<<(unsigned)(nX / 4 / 256), 256>>>(x,  xh,  xl,  nX);
    split_f32<<<(unsigned)(nW / 4 / 256), 256>>>(Wq, Wqh, Wql, nW);
    split_f32<<<(unsigned)(nW / 4 / 256), 256>>>(Wk, Wkh, Wkl, nW);
    round_f32<<<(unsigned)(nW / 4 / 256), 256>>>(Wv, Wvh, nW);

    // 1) Q = xh @ (Wqh+Wql)^T + bq -> Qh;  K = xh @ (Wkh+Wkl)^T + bk -> Kh
    {
        dim3 g(HN / 128, MTOT / 256, 1);
        mma_gemm<<<g, 512, smem2>>>(xh, Wqh, Wql, 2, bq, 1, 1.0f,
                                    nullptr, Qh, 1, HN, HN, 0, 0, 0);
        mma_gemm<<<g, 512, smem2>>>(xh, Wkh, Wkl, 2, bk, 1, 1.0f,
                                    nullptr, Kh, 1, HN, HN, 0, 0, 0);
    }
    // 2) Vt_b = Wvh @ (xh+xl)_b^T + bv[row] -> Vth
    {
        dim3 g(SN / 128, HN / 256, BN);
        mma_gemm<<<g, 512, smem2>>>(Wvh, xh, xl, 2, bv, 2, 1.0f,
                                    nullptr, Vth, 1, HN, SN,
                                    0, (size_t)SN * HN, (size_t)HN * SN);
    }
    // 3) scores = Qh_b @ Kh_b^T / 32 -> fp32 P   (1-pass)
    {
        dim3 g(SN / 128, SN / 256, BN);
        mma_gemm<<<g, 512, smem1>>>(Qh, Kh, nullptr, 1, nullptr, 0, 0.03125f,
                                    P, nullptr, 0, HN, SN,
                                    (size_t)SN * HN, (size_t)SN * HN, (size_t)SN * SN);
    }
    // 4) softmax rows -> Ph
    softmax_h<<<BN * SN, 256>>>(P, Ph, SN);

    // 5) out = Ph_b @ Vth_b^T -> fp32   (1-pass)
    {
        dim3 g(HN / 128, SN / 256, BN);
        mma_gemm<<<g, 512, smem1>>>(Ph, Vth, nullptr, 1, nullptr, 0, 1.0f,
                                    out, nullptr, 0, SN, HN,
                                    (size_t)SN * SN, (size_t)HN * SN, (size_t)SN * HN);
    }
}

// round 12
// speedup vs baseline: 6.7911x; 1.1861x over previous
#include <cuda_runtime.h>
#include <cuda_fp16.h>
#include <math.h>
#include <stdint.h>

#define BN 4
#define SN 2048
#define HN 1024
#define MTOT (BN * SN)

// ---------------------------------------------------------------------------
// Scratch (__device__ globals; allocation-free rule)
// ---------------------------------------------------------------------------
__device__ __half g_xh[(size_t)MTOT * HN], g_xl[(size_t)MTOT * HN];
__device__ __half g_Wqh[(size_t)HN * HN];
__device__ __half g_Wkh[(size_t)HN * HN];
__device__ __half g_Wvh[(size_t)HN * HN];
__device__ __half g_Qh[(size_t)MTOT * HN];
__device__ __half g_KhA[(size_t)MTOT * HN];
__device__ __half g_Vth[(size_t)BN * HN * SN];
__device__ float  g_P[(size_t)BN * SN * SN];
__device__ __half g_Ph[(size_t)BN * SN * SN];

// ---------------------------------------------------------------------------
// Helpers (compute_103-safe: ldmatrix + mma.sync + cp.async only)
// ---------------------------------------------------------------------------
__device__ __forceinline__ uint32_t smem_u32(const void* p) {
    uint32_t a;
    asm("{ .reg .u64 t; cvta.to.shared.u64 t, %1; cvt.u32.u64 %0, t; }" : "=r"(a) : "l"(p));
    return a;
}
__device__ __forceinline__ void ldsm_x4(uint32_t* r, uint32_t a) {
    asm volatile("ldmatrix.sync.aligned.m8n8.x4.shared.b16 {%0,%1,%2,%3}, [%4];"
                 : "=r"(r[0]), "=r"(r[1]), "=r"(r[2]), "=r"(r[3]) : "r"(a));
}
__device__ __forceinline__ void mma_f16(float* c, const uint32_t* a,
                                        uint32_t b0, uint32_t b1) {
    asm volatile("mma.sync.aligned.m16n8k16.row.col.f32.f16.f16.f32 "
                 "{%0,%1,%2,%3}, {%4,%5,%6,%7}, {%8,%9}, {%0,%1,%2,%3};"
                 : "+f"(c[0]), "+f"(c[1]), "+f"(c[2]), "+f"(c[3])
                 : "r"(a[0]), "r"(a[1]), "r"(a[2]), "r"(a[3]), "r"(b0), "r"(b1));
}
#define CP_COMMIT() asm volatile("cp.async.commit_group;" ::: "memory")
#define CP_WAIT1()  asm volatile("cp.async.wait_group 1;" ::: "memory")
#define CP_WAIT0()  asm volatile("cp.async.wait_group 0;" ::: "memory")

// ---------------------------------------------------------------------------
// NT GEMM via mma.sync fp16:
//   npass=2: C = scale * sum_k A[m,k]*(Bh+Bl)[n,k] + bias   (split-B)
//   npass=1: C = scale * sum_k A[m,k]*Bh[n,k] + bias        (plain fp16)
// Tile 256x128, BK=64 (128B rows, SW128 xor swizzle), 512 threads,
// warp grid 4(m)x4(n), warp tile 64x32. 3-stage cp.async pipeline.
// biasMode: 0 none, 1 bias[col], 2 bias[row].
// outMode: 0 fp32, 1 fp16 hi only.
// Requires M%256==0, N%128==0, K%64==0.
// ---------------------------------------------------------------------------
#define A_BYTES 32768              // 256 rows x 128B
#define B_BYTES 16384              // 128 rows x 128B
#define NSTAGE  3

__global__ __launch_bounds__(512, 1)
void mma_gemm(const __half* __restrict__ A, const __half* __restrict__ Bh,
              const __half* __restrict__ Bl, int npass,
              const float* __restrict__ bias, int biasMode, float scale,
              float* __restrict__ Cf, __half* __restrict__ Ch,
              int outMode, int K, int ldc,
              size_t szA, size_t szB, size_t szC)
{
    extern __shared__ char smem[];
    const uint32_t sb = smem_u32(smem);
    const int tid = threadIdx.x, lane = tid & 31, wid = tid >> 5;
    const int wm = wid & 3, wn = wid >> 2;   // 4 x 4 warp grid, warp tile 64x32
    const uint32_t stageBytes = A_BYTES + (npass == 2 ? 2 : 1) * B_BYTES;

    A  += (size_t)blockIdx.z * szA;
    Bh += (size_t)blockIdx.z * szB;
    if (npass == 2) Bl += (size_t)blockIdx.z * szB;
    if (outMode == 0) Cf += (size_t)blockIdx.z * szC;
    else              Ch += (size_t)blockIdx.z * szC;

    const int rowBase = blockIdx.y * 256;
    const int colBase = blockIdx.x * 128;

    const __half* tA  = A  + (size_t)rowBase * K;
    const __half* tBh = Bh + (size_t)colBase * K;
    const __half* tBl = (npass == 2) ? (Bl + (size_t)colBase * K) : tBh;

    const int NK = K >> 6;

    // stage loaders: 16B cp.async, SW128 swizzle
    auto load_A = [&](uint32_t dst, const __half* g) {
        #pragma unroll
        for (int i = 0; i < 4; i++) {
            int idx = i * 512 + tid;
            int row = idx >> 3;
            int kb  = idx & 7;
            uint32_t off = row * 128 + kb * 16;
            uint32_t sw  = off ^ ((off >> 3) & 0x70);
            const void* src = (const void*)(g + (size_t)row * K + kb * 8);
            asm volatile("cp.async.cg.shared.global [%0], [%1], 16;"
                         :: "r"(dst + sw), "l"(src));
        }
    };
    auto load_B = [&](uint32_t dst, const __half* g) {
        #pragma unroll
        for (int i = 0; i < 2; i++) {
            int idx = i * 512 + tid;
            int row = idx >> 3;
            int kb  = idx & 7;
            uint32_t off = row * 128 + kb * 16;
            uint32_t sw  = off ^ ((off >> 3) & 0x70);
            const void* src = (const void*)(g + (size_t)row * K + kb * 8);
            asm volatile("cp.async.cg.shared.global [%0], [%1], 16;"
                         :: "r"(dst + sw), "l"(src));
        }
    };
    auto load_stage = [&](int buf, int c) {
        uint32_t st = sb + buf * stageBytes;
        size_t ko = (size_t)c * 64;
        load_A(st, tA + ko);
        load_B(st + A_BYTES, tBh + ko);
        if (npass == 2) load_B(st + A_BYTES + B_BYTES, tBl + ko);
        CP_COMMIT();
    };

    // accumulators: 4 m16-tiles x 4 n8-cols x 4 = 64 fp32
    float acc[4][4][4];
    #pragma unroll
    for (int i = 0; i < 4; i++)
        #pragma unroll
        for (int j = 0; j < 4; j++)
            #pragma unroll
            for (int q = 0; q < 4; q++) acc[i][j][q] = 0.0f;

    // ldmatrix lane addressing
    const int lm = lane & 15;
    const int lk = lane >> 4;
    int rA[4], rB[2];
    #pragma unroll
    for (int i = 0; i < 4; i++) rA[i] = wm * 64 + i * 16 + lm;
    #pragma unroll
    for (int g = 0; g < 2; g++) rB[g] = wn * 32 + g * 16 + lm;

    // prologue: fill 2 of 3 stages
    load_stage(0, 0);
    if (NK > 1) load_stage(1, 1);

    int buf = 0;
    for (int c = 0; c < NK; c++) {
        if (c < NK - 1) { CP_WAIT1(); } else { CP_WAIT0(); }
        __syncthreads();
        if (c + 2 < NK) {
            int nb = buf + 2; if (nb >= NSTAGE) nb -= NSTAGE;
            load_stage(nb, c + 2);
        }

        const uint32_t stage = sb + buf * stageBytes;
        #pragma unroll
        for (int ks = 0; ks < 4; ks++) {
            const int atom = ks * 2 + lk;
            uint32_t a[4][4];
            #pragma unroll
            for (int i = 0; i < 4; i++)
                ldsm_x4(a[i], stage + rA[i] * 128 + ((atom ^ (rA[i] & 7)) << 4));
            uint32_t bh[2][4];
            #pragma unroll
            for (int g = 0; g < 2; g++)
                ldsm_x4(bh[g], stage + A_BYTES + rB[g] * 128 + ((atom ^ (rB[g] & 7)) << 4));
            // pass 0: A·Bh
            #pragma unroll
            for (int i = 0; i < 4; i++)
                #pragma unroll
                for (int g = 0; g < 2; g++) {
                    mma_f16(acc[i][2 * g + 0], a[i], bh[g][0], bh[g][2]);
                    mma_f16(acc[i][2 * g + 1], a[i], bh[g][1], bh[g][3]);
                }
            // pass 1: A·Bl (split-B only)
            if (npass == 2) {
                uint32_t bl[2][4];
                #pragma unroll
                for (int g = 0; g < 2; g++)
                    ldsm_x4(bl[g], stage + A_BYTES + B_BYTES + rB[g] * 128 + ((atom ^ (rB[g] & 7)) << 4));
                #pragma unroll
                for (int i = 0; i < 4; i++)
                    #pragma unroll
                    for (int g = 0; g < 2; g++) {
                        mma_f16(acc[i][2 * g + 0], a[i], bl[g][0], bl[g][2]);
                        mma_f16(acc[i][2 * g + 1], a[i], bl[g][1], bl[g][3]);
                    }
            }
        }
        buf++; if (buf >= NSTAGE) buf = 0;
    }

    // epilogue: scale + bias
    #pragma unroll
    for (int i = 0; i < 4; i++) {
        #pragma unroll
        for (int half = 0; half < 2; half++) {
            const int row = rowBase + wm * 64 + i * 16 + (lane >> 2) + half * 8;
            const float rb = (biasMode == 2) ? bias[row] : 0.0f;
            #pragma unroll
            for (int j = 0; j < 4; j++) {
                const int col = colBase + wn * 32 + j * 8 + (lane & 3) * 2;
                float v0 = acc[i][j][half * 2 + 0] * scale;
                float v1 = acc[i][j][half * 2 + 1] * scale;
                if (biasMode == 1) { v0 += bias[col]; v1 += bias[col + 1]; }
                else               { v0 += rb;        v1 += rb; }
                const size_t base = (size_t)row * ldc + col;
                if (outMode == 0) {
                    float2 o; o.x = v0; o.y = v1;
                    *(float2*)(Cf + base) = o;
                } else {
                    __half2 hh; hh.x = __float2half_rn(v0); hh.y = __float2half_rn(v1);
                    *(__half2*)(Ch + base) = hh;
                }
            }
        }
    }
}

// ---------------------------------------------------------------------------
// split fp32 -> fp16 hi/lo
// ---------------------------------------------------------------------------
__global__ __launch_bounds__(256) void split_f32(
    const float* __restrict__ in, __half* __restrict__ hi,
    __half* __restrict__ lo, size_t n)
{
    size_t i = ((size_t)blockIdx.x * 256 + threadIdx.x) * 4;
    if (i >= n) return;
    float4 v = *(const float4*)(in + i);
    __half h0 = __float2half_rn(v.x), h1 = __float2half_rn(v.y);
    __half h2 = __float2half_rn(v.z), h3 = __float2half_rn(v.w);
    __half2 ha; ha.x = h0; ha.y = h1;
    __half2 hb; hb.x = h2; hb.y = h3;
    __half2 la, lb;
    la.x = __float2half_rn(v.x - __half2float(h0));
    la.y = __float2half_rn(v.y - __half2float(h1));
    lb.x = __float2half_rn(v.z - __half2float(h2));
    lb.y = __float2half_rn(v.w - __half2float(h3));
    *(__half2*)(hi + i) = ha; *(__half2*)(hi + i + 2) = hb;
    *(__half2*)(lo + i) = la; *(__half2*)(lo + i + 2) = lb;
}

// fp32 -> fp16 hi only
__global__ __launch_bounds__(256) void round_f32(
    const float* __restrict__ in, __half* __restrict__ hi, size_t n)
{
    size_t i = ((size_t)blockIdx.x * 256 + threadIdx.x) * 4;
    if (i >= n) return;
    float4 v = *(const float4*)(in + i);
    __half2 ha; ha.x = __float2half_rn(v.x); ha.y = __float2half_rn(v.y);
    __half2 hb; hb.x = __float2half_rn(v.z); hb.y = __float2half_rn(v.w);
    *(__half2*)(hi + i) = ha; *(__half2*)(hi + i + 2) = hb;
}

// ---------------------------------------------------------------------------
// row softmax: fp32 in, fp16 hi out. One block per row of 2048.
// ---------------------------------------------------------------------------
__global__ __launch_bounds__(256) void softmax_h(
    const float* __restrict__ P, __half* __restrict__ Ph, int n)
{
    const float* row = P + (size_t)blockIdx.x * n;
    __half* oh = Ph + (size_t)blockIdx.x * n;
    const int tid = threadIdx.x, lane = tid & 31, wd = tid >> 5;
    __shared__ float red[8];

    float v[8]; float m = -INFINITY;
    #pragma unroll
    for (int i = 0; i < 8; i++) { v[i] = row[tid + i * 256]; m = fmaxf(m, v[i]); }
    #pragma unroll
    for (int o = 16; o > 0; o >>= 1) m = fmaxf(m, __shfl_xor_sync(~0u, m, o));
    if (lane == 0) red[wd] = m;
    __syncthreads();
    float mb = red[0];
    #pragma unroll
    for (int w = 1; w < 8; w++) mb = fmaxf(mb, red[w]);
    __syncthreads();

    float s = 0.0f;
    #pragma unroll
    for (int i = 0; i < 8; i++) { v[i] = __expf(v[i] - mb); s += v[i]; }
    #pragma unroll
    for (int o = 16; o > 0; o >>= 1) s += __shfl_xor_sync(~0u, s, o);
    if (lane == 0) red[wd] = s;
    __syncthreads();
    float sb = 0.0f;
    #pragma unroll
    for (int w = 0; w < 8; w++) sb += red[w];
    const float r = 1.0f / sb;

    #pragma unroll
    for (int i = 0; i < 8; i++)
        oh[tid + i * 256] = __float2half_rn(v[i] * r);
}

// ---------------------------------------------------------------------------
extern "C" void kernel_launch(void* const* d_in, const int* in_sizes, int n_in,
                              void* d_out, int out_size)
{
    (void)in_sizes; (void)n_in; (void)out_size;
    const float* x  = (const float*)d_in[0];
    const float* Wq = (const float*)d_in[1];
    const float* bq = (const float*)d_in[2];
    const float* Wk = (const float*)d_in[3];
    const float* bk = (const float*)d_in[4];
    const float* Wv = (const float*)d_in[5];
    const float* bv = (const float*)d_in[6];
    float* out = (float*)d_out;

    const int smem2 = NSTAGE * (A_BYTES + 2 * B_BYTES);   // 192 KB (2-pass)
    const int smem1 = NSTAGE * (A_BYTES + B_BYTES);       // 144 KB (1-pass)
    cudaFuncSetAttribute(mma_gemm, cudaFuncAttributeMaxDynamicSharedMemorySize, smem2);

    __half *xh, *xl, *Wqh, *Wkh, *Wvh;
    __half *Qh, *Kh, *Vth, *Ph;
    float *P;
    cudaGetSymbolAddress((void**)&xh, g_xh);   cudaGetSymbolAddress((void**)&xl, g_xl);
    cudaGetSymbolAddress((void**)&Wqh, g_Wqh);
    cudaGetSymbolAddress((void**)&Wkh, g_Wkh);
    cudaGetSymbolAddress((void**)&Wvh, g_Wvh);
    cudaGetSymbolAddress((void**)&Qh, g_Qh);
    cudaGetSymbolAddress((void**)&Kh, g_KhA);
    cudaGetSymbolAddress((void**)&Vth, g_Vth);
    cudaGetSymbolAddress((void**)&P, g_P);
    cudaGetSymbolAddress((void**)&Ph, g_Ph);

    const size_t nX = (size_t)MTOT * HN;
    const size_t nW = (size_t)HN * HN;

    // 0) split x (V chain stays 2-pass); round weights to fp16
    split_f32<<<(unsigned)(nX / 4 / 256), 256>>>(x,  xh,  xl,  nX);
    round_f32<<<(unsigned)(nW / 4 / 256), 256>>>(Wq, Wqh, nW);
    round_f32<<<(unsigned)(nW / 4 / 256), 256>>>(Wk, Wkh, nW);
    round_f32<<<(unsigned)(nW / 4 / 256), 256>>>(Wv, Wvh, nW);

    // 1) Q = xh @ Wqh^T + bq -> Qh;  K = xh @ Wkh^T + bk -> Kh   (1-pass)
    {
        dim3 g(HN / 128, MTOT / 256, 1);
        mma_gemm<<<g, 512, smem1>>>(xh, Wqh, nullptr, 1, bq, 1, 1.0f,
                                    nullptr, Qh, 1, HN, HN, 0, 0, 0);
        mma_gemm<<<g, 512, smem1>>>(xh, Wkh, nullptr, 1, bk, 1, 1.0f,
                                    nullptr, Kh, 1, HN, HN, 0, 0, 0);
    }
    // 2) Vt_b = Wvh @ (xh+xl)_b^T + bv[row] -> Vth   (2-pass, exact x)
    {
        dim3 g(SN / 128, HN / 256, BN);
        mma_gemm<<<g, 512, smem2>>>(Wvh, xh, xl, 2, bv, 2, 1.0f,
                                    nullptr, Vth, 1, HN, SN,
                                    0, (size_t)SN * HN, (size_t)HN * SN);
    }
    // 3) scores = Qh_b @ Kh_b^T / 32 -> fp32 P   (1-pass)
    {
        dim3 g(SN / 128, SN / 256, BN);
        mma_gemm<<<g, 512, smem1>>>(Qh, Kh, nullptr, 1, nullptr, 0, 0.03125f,
                                    P, nullptr, 0, HN, SN,
                                    (size_t)SN * HN, (size_t)SN * HN, (size_t)SN * SN);
    }
    // 4) softmax rows -> Ph
    softmax_h<<<BN * SN, 256>>>(P, Ph, SN);

    // 5) out = Ph_b @ Vth_b^T -> fp32   (1-pass)
    {
        dim3 g(HN / 128, SN / 256, BN);
        mma_gemm<<<g, 512, smem1>>>(Ph, Vth, nullptr, 1, nullptr, 0, 1.0f,
                                    out, nullptr, 0, SN, HN,
                                    (size_t)SN * SN, (size_t)HN * SN, (size_t)SN * HN);
    }
}

// round 13
// speedup vs baseline: 7.2530x; 1.0680x over previous
#include <cuda_runtime.h>
#include <cuda_fp16.h>
#include <math.h>
#include <stdint.h>

#define BN 4
#define SN 2048
#define HN 1024
#define MTOT (BN * SN)

// ---------------------------------------------------------------------------
// Scratch (__device__ globals; allocation-free rule)
// ---------------------------------------------------------------------------
__device__ __half g_xh[(size_t)MTOT * HN];
__device__ __half g_Wqh[(size_t)HN * HN];
__device__ __half g_Wkh[(size_t)HN * HN];
__device__ __half g_Wvh[(size_t)HN * HN];
__device__ __half g_Qh[(size_t)MTOT * HN];
__device__ __half g_KhA[(size_t)MTOT * HN];
__device__ __half g_Vth[(size_t)BN * HN * SN];
__device__ float  g_P[(size_t)BN * SN * SN];
__device__ __half g_Ph[(size_t)BN * SN * SN];

// ---------------------------------------------------------------------------
// Helpers (compute_103-safe: ldmatrix + mma.sync + cp.async only)
// ---------------------------------------------------------------------------
__device__ __forceinline__ uint32_t smem_u32(const void* p) {
    uint32_t a;
    asm("{ .reg .u64 t; cvta.to.shared.u64 t, %1; cvt.u32.u64 %0, t; }" : "=r"(a) : "l"(p));
    return a;
}
__device__ __forceinline__ void ldsm_x4(uint32_t* r, uint32_t a) {
    asm volatile("ldmatrix.sync.aligned.m8n8.x4.shared.b16 {%0,%1,%2,%3}, [%4];"
                 : "=r"(r[0]), "=r"(r[1]), "=r"(r[2]), "=r"(r[3]) : "r"(a));
}
__device__ __forceinline__ void mma_f16(float* c, const uint32_t* a,
                                        uint32_t b0, uint32_t b1) {
    asm volatile("mma.sync.aligned.m16n8k16.row.col.f32.f16.f16.f32 "
                 "{%0,%1,%2,%3}, {%4,%5,%6,%7}, {%8,%9}, {%0,%1,%2,%3};"
                 : "+f"(c[0]), "+f"(c[1]), "+f"(c[2]), "+f"(c[3])
                 : "r"(a[0]), "r"(a[1]), "r"(a[2]), "r"(a[3]), "r"(b0), "r"(b1));
}
#define CP_COMMIT() asm volatile("cp.async.commit_group;" ::: "memory")
#define CP_WAIT1()  asm volatile("cp.async.wait_group 1;" ::: "memory")
#define CP_WAIT0()  asm volatile("cp.async.wait_group 0;" ::: "memory")

// ---------------------------------------------------------------------------
// NT GEMM via mma.sync fp16 (plain 1-pass):
//   C[M,N] = scale * sum_k A[m,k]*B[n,k] + bias
// Tile 256x128, BK=64 (128B rows, SW128 xor swizzle), 512 threads,
// warp grid 4(m)x4(n), warp tile 64x32. 3-stage cp.async pipeline.
// biasMode: 0 none, 1 bias[col], 2 bias[row].
// outMode: 0 fp32, 1 fp16.
// Requires M%256==0, N%128==0, K%64==0.
// ---------------------------------------------------------------------------
#define A_BYTES     32768              // 256 rows x 128B
#define B_BYTES     16384              // 128 rows x 128B
#define STAGE_BYTES (A_BYTES + B_BYTES)
#define NSTAGE      3

__global__ __launch_bounds__(512, 1)
void mma_gemm(const __half* __restrict__ A, const __half* __restrict__ B,
              const float* __restrict__ bias, int biasMode, float scale,
              float* __restrict__ Cf, __half* __restrict__ Ch,
              int outMode, int K, int ldc,
              size_t szA, size_t szB, size_t szC)
{
    extern __shared__ char smem[];
    const uint32_t sb = smem_u32(smem);
    const int tid = threadIdx.x, lane = tid & 31, wid = tid >> 5;
    const int wm = wid & 3, wn = wid >> 2;   // 4 x 4 warp grid, warp tile 64x32

    A += (size_t)blockIdx.z * szA;
    B += (size_t)blockIdx.z * szB;
    if (outMode == 0) Cf += (size_t)blockIdx.z * szC;
    else              Ch += (size_t)blockIdx.z * szC;

    const int rowBase = blockIdx.y * 256;
    const int colBase = blockIdx.x * 128;

    const __half* tA = A + (size_t)rowBase * K;
    const __half* tB = B + (size_t)colBase * K;

    const int NK = K >> 6;

    // stage loaders: 16B cp.async, SW128 swizzle
    auto load_A = [&](uint32_t dst, const __half* g) {
        #pragma unroll
        for (int i = 0; i < 4; i++) {
            int idx = i * 512 + tid;
            int row = idx >> 3;
            int kb  = idx & 7;
            uint32_t off = row * 128 + kb * 16;
            uint32_t sw  = off ^ ((off >> 3) & 0x70);
            const void* src = (const void*)(g + (size_t)row * K + kb * 8);
            asm volatile("cp.async.cg.shared.global [%0], [%1], 16;"
                         :: "r"(dst + sw), "l"(src));
        }
    };
    auto load_B = [&](uint32_t dst, const __half* g) {
        #pragma unroll
        for (int i = 0; i < 2; i++) {
            int idx = i * 512 + tid;
            int row = idx >> 3;
            int kb  = idx & 7;
            uint32_t off = row * 128 + kb * 16;
            uint32_t sw  = off ^ ((off >> 3) & 0x70);
            const void* src = (const void*)(g + (size_t)row * K + kb * 8);
            asm volatile("cp.async.cg.shared.global [%0], [%1], 16;"
                         :: "r"(dst + sw), "l"(src));
        }
    };
    auto load_stage = [&](int buf, int c) {
        uint32_t st = sb + buf * STAGE_BYTES;
        size_t ko = (size_t)c * 64;
        load_A(st, tA + ko);
        load_B(st + A_BYTES, tB + ko);
        CP_COMMIT();
    };

    // accumulators: 4 m16-tiles x 4 n8-cols x 4 = 64 fp32
    float acc[4][4][4];
    #pragma unroll
    for (int i = 0; i < 4; i++)
        #pragma unroll
        for (int j = 0; j < 4; j++)
            #pragma unroll
            for (int q = 0; q < 4; q++) acc[i][j][q] = 0.0f;

    // ldmatrix lane addressing
    const int lm = lane & 15;
    const int lk = lane >> 4;
    int rA[4], rB[2];
    #pragma unroll
    for (int i = 0; i < 4; i++) rA[i] = wm * 64 + i * 16 + lm;
    #pragma unroll
    for (int g = 0; g < 2; g++) rB[g] = wn * 32 + g * 16 + lm;

    // prologue: fill 2 of 3 stages
    load_stage(0, 0);
    if (NK > 1) load_stage(1, 1);

    int buf = 0;
    for (int c = 0; c < NK; c++) {
        if (c < NK - 1) { CP_WAIT1(); } else { CP_WAIT0(); }
        __syncthreads();
        if (c + 2 < NK) {
            int nb = buf + 2; if (nb >= NSTAGE) nb -= NSTAGE;
            load_stage(nb, c + 2);
        }

        const uint32_t stage = sb + buf * STAGE_BYTES;
        #pragma unroll
        for (int ks = 0; ks < 4; ks++) {
            const int atom = ks * 2 + lk;
            uint32_t a[4][4];
            #pragma unroll
            for (int i = 0; i < 4; i++)
                ldsm_x4(a[i], stage + rA[i] * 128 + ((atom ^ (rA[i] & 7)) << 4));
            uint32_t bf[2][4];
            #pragma unroll
            for (int g = 0; g < 2; g++)
                ldsm_x4(bf[g], stage + A_BYTES + rB[g] * 128 + ((atom ^ (rB[g] & 7)) << 4));
            #pragma unroll
            for (int i = 0; i < 4; i++)
                #pragma unroll
                for (int g = 0; g < 2; g++) {
                    mma_f16(acc[i][2 * g + 0], a[i], bf[g][0], bf[g][2]);
                    mma_f16(acc[i][2 * g + 1], a[i], bf[g][1], bf[g][3]);
                }
        }
        buf++; if (buf >= NSTAGE) buf = 0;
    }

    // epilogue: scale + bias
    #pragma unroll
    for (int i = 0; i < 4; i++) {
        #pragma unroll
        for (int half = 0; half < 2; half++) {
            const int row = rowBase + wm * 64 + i * 16 + (lane >> 2) + half * 8;
            const float rb = (biasMode == 2) ? bias[row] : 0.0f;
            #pragma unroll
            for (int j = 0; j < 4; j++) {
                const int col = colBase + wn * 32 + j * 8 + (lane & 3) * 2;
                float v0 = acc[i][j][half * 2 + 0] * scale;
                float v1 = acc[i][j][half * 2 + 1] * scale;
                if (biasMode == 1) { v0 += bias[col]; v1 += bias[col + 1]; }
                else               { v0 += rb;        v1 += rb; }
                const size_t base = (size_t)row * ldc + col;
                if (outMode == 0) {
                    float2 o; o.x = v0; o.y = v1;
                    *(float2*)(Cf + base) = o;
                } else {
                    __half2 hh; hh.x = __float2half_rn(v0); hh.y = __float2half_rn(v1);
                    *(__half2*)(Ch + base) = hh;
                }
            }
        }
    }
}

// ---------------------------------------------------------------------------
// fp32 -> fp16 round
// ---------------------------------------------------------------------------
__global__ __launch_bounds__(256) void round_f32(
    const float* __restrict__ in, __half* __restrict__ hi, size_t n)
{
    size_t i = ((size_t)blockIdx.x * 256 + threadIdx.x) * 4;
    if (i >= n) return;
    float4 v = *(const float4*)(in + i);
    __half2 ha; ha.x = __float2half_rn(v.x); ha.y = __float2half_rn(v.y);
    __half2 hb; hb.x = __float2half_rn(v.z); hb.y = __float2half_rn(v.w);
    *(__half2*)(hi + i) = ha; *(__half2*)(hi + i + 2) = hb;
}

// ---------------------------------------------------------------------------
// row softmax: fp32 in, fp16 out. One block per row of 2048.
// ---------------------------------------------------------------------------
__global__ __launch_bounds__(256) void softmax_h(
    const float* __restrict__ P, __half* __restrict__ Ph, int n)
{
    const float* row = P + (size_t)blockIdx.x * n;
    __half* oh = Ph + (size_t)blockIdx.x * n;
    const int tid = threadIdx.x, lane = tid & 31, wd = tid >> 5;
    __shared__ float red[8];

    float v[8]; float m = -INFINITY;
    #pragma unroll
    for (int i = 0; i < 8; i++) { v[i] = row[tid + i * 256]; m = fmaxf(m, v[i]); }
    #pragma unroll
    for (int o = 16; o > 0; o >>= 1) m = fmaxf(m, __shfl_xor_sync(~0u, m, o));
    if (lane == 0) red[wd] = m;
    __syncthreads();
    float mb = red[0];
    #pragma unroll
    for (int w = 1; w < 8; w++) mb = fmaxf(mb, red[w]);
    __syncthreads();

    float s = 0.0f;
    #pragma unroll
    for (int i = 0; i < 8; i++) { v[i] = __expf(v[i] - mb); s += v[i]; }
    #pragma unroll
    for (int o = 16; o > 0; o >>= 1) s += __shfl_xor_sync(~0u, s, o);
    if (lane == 0) red[wd] = s;
    __syncthreads();
    float sb = 0.0f;
    #pragma unroll
    for (int w = 0; w < 8; w++) sb += red[w];
    const float r = 1.0f / sb;

    #pragma unroll
    for (int i = 0; i < 8; i++)
        oh[tid + i * 256] = __float2half_rn(v[i] * r);
}

// ---------------------------------------------------------------------------
extern "C" void kernel_launch(void* const* d_in, const int* in_sizes, int n_in,
                              void* d_out, int out_size)
{
    (void)in_sizes; (void)n_in; (void)out_size;
    const float* x  = (const float*)d_in[0];
    const float* Wq = (const float*)d_in[1];
    const float* bq = (const float*)d_in[2];
    const float* Wk = (const float*)d_in[3];
    const float* bk = (const float*)d_in[4];
    const float* Wv = (const float*)d_in[5];
    const float* bv = (const float*)d_in[6];
    float* out = (float*)d_out;

    const int smem = NSTAGE * STAGE_BYTES;   // 144 KB
    cudaFuncSetAttribute(mma_gemm, cudaFuncAttributeMaxDynamicSharedMemorySize, smem);

    __half *xh, *Wqh, *Wkh, *Wvh, *Qh, *Kh, *Vth, *Ph;
    float *P;
    cudaGetSymbolAddress((void**)&xh, g_xh);
    cudaGetSymbolAddress((void**)&Wqh, g_Wqh);
    cudaGetSymbolAddress((void**)&Wkh, g_Wkh);
    cudaGetSymbolAddress((void**)&Wvh, g_Wvh);
    cudaGetSymbolAddress((void**)&Qh, g_Qh);
    cudaGetSymbolAddress((void**)&Kh, g_KhA);
    cudaGetSymbolAddress((void**)&Vth, g_Vth);
    cudaGetSymbolAddress((void**)&P, g_P);
    cudaGetSymbolAddress((void**)&Ph, g_Ph);

    const size_t nX = (size_t)MTOT * HN;
    const size_t nW = (size_t)HN * HN;

    // 0) round inputs to fp16
    round_f32<<<(unsigned)(nX / 4 / 256), 256>>>(x,  xh,  nX);
    round_f32<<<(unsigned)(nW / 4 / 256), 256>>>(Wq, Wqh, nW);
    round_f32<<<(unsigned)(nW / 4 / 256), 256>>>(Wk, Wkh, nW);
    round_f32<<<(unsigned)(nW / 4 / 256), 256>>>(Wv, Wvh, nW);

    // 1) Q = xh @ Wqh^T + bq -> Qh;  K = xh @ Wkh^T + bk -> Kh
    {
        dim3 g(HN / 128, MTOT / 256, 1);
        mma_gemm<<<g, 512, smem>>>(xh, Wqh, bq, 1, 1.0f,
                                   nullptr, Qh, 1, HN, HN, 0, 0, 0);
        mma_gemm<<<g, 512, smem>>>(xh, Wkh, bk, 1, 1.0f,
                                   nullptr, Kh, 1, HN, HN, 0, 0, 0);
    }
    // 2) Vt_b = Wvh @ xh_b^T + bv[row] -> Vth
    {
        dim3 g(SN / 128, HN / 256, BN);
        mma_gemm<<<g, 512, smem>>>(Wvh, xh, bv, 2, 1.0f,
                                   nullptr, Vth, 1, HN, SN,
                                   0, (size_t)SN * HN, (size_t)HN * SN);
    }
    // 3) scores = Qh_b @ Kh_b^T / 32 -> fp32 P
    {
        dim3 g(SN / 128, SN / 256, BN);
        mma_gemm<<<g, 512, smem>>>(Qh, Kh, nullptr, 0, 0.03125f,
                                   P, nullptr, 0, HN, SN,
                                   (size_t)SN * HN, (size_t)SN * HN, (size_t)SN * SN);
    }
    // 4) softmax rows -> Ph
    softmax_h<<<BN * SN, 256>>>(P, Ph, SN);

    // 5) out = Ph_b @ Vth_b^T -> fp32
    {
        dim3 g(HN / 128, SN / 256, BN);
        mma_gemm<<<g, 512, smem>>>(Ph, Vth, nullptr, 0, 1.0f,
                                   out, nullptr, 0, SN, HN,
                                   (size_t)SN * SN, (size_t)HN * SN, (size_t)SN * HN);
    }
}

// round 14
// speedup vs baseline: 7.4482x; 1.0269x over previous
#include <cuda_runtime.h>
#include <cuda_fp16.h>
#include <math.h>
#include <stdint.h>

#define BN 4
#define SN 2048
#define HN 1024
#define MTOT (BN * SN)

// ---------------------------------------------------------------------------
// Scratch (__device__ globals; allocation-free rule)
// ---------------------------------------------------------------------------
__device__ __half g_xh[(size_t)MTOT * HN];
__device__ __half g_Wqh[(size_t)HN * HN];
__device__ __half g_Wkh[(size_t)HN * HN];
__device__ __half g_Wvh[(size_t)HN * HN];
__device__ __half g_Qh[(size_t)MTOT * HN];
__device__ __half g_KhA[(size_t)MTOT * HN];
__device__ __half g_Vth[(size_t)BN * HN * SN];
__device__ float  g_P[(size_t)BN * SN * SN];
__device__ __half g_Ph[(size_t)BN * SN * SN];

// ---------------------------------------------------------------------------
// Helpers (compute_103-safe: ldmatrix + mma.sync + cp.async only)
// ---------------------------------------------------------------------------
__device__ __forceinline__ uint32_t smem_u32(const void* p) {
    uint32_t a;
    asm("{ .reg .u64 t; cvta.to.shared.u64 t, %1; cvt.u32.u64 %0, t; }" : "=r"(a) : "l"(p));
    return a;
}
__device__ __forceinline__ void ldsm_x4(uint32_t* r, uint32_t a) {
    asm volatile("ldmatrix.sync.aligned.m8n8.x4.shared.b16 {%0,%1,%2,%3}, [%4];"
                 : "=r"(r[0]), "=r"(r[1]), "=r"(r[2]), "=r"(r[3]) : "r"(a));
}
__device__ __forceinline__ void mma_f16(float* c, const uint32_t* a,
                                        uint32_t b0, uint32_t b1) {
    asm volatile("mma.sync.aligned.m16n8k16.row.col.f32.f16.f16.f32 "
                 "{%0,%1,%2,%3}, {%4,%5,%6,%7}, {%8,%9}, {%0,%1,%2,%3};"
                 : "+f"(c[0]), "+f"(c[1]), "+f"(c[2]), "+f"(c[3])
                 : "r"(a[0]), "r"(a[1]), "r"(a[2]), "r"(a[3]), "r"(b0), "r"(b1));
}
#define CP_COMMIT() asm volatile("cp.async.commit_group;" ::: "memory")
#define CP_WAIT0()  asm volatile("cp.async.wait_group 0;" ::: "memory")
#define CP_WAIT1()  asm volatile("cp.async.wait_group 1;" ::: "memory")
#define CP_WAIT2()  asm volatile("cp.async.wait_group 2;" ::: "memory")

// ---------------------------------------------------------------------------
// NT GEMM via mma.sync fp16 (plain 1-pass):
//   C[M,N] = scale * sum_k A[m,k]*B[n,k] + bias
// Tile 256x128, BK=64 (128B rows, SW128 xor swizzle), 512 threads,
// warp grid 4(m)x4(n), warp tile 64x32. 3-stage cp.async pipeline.
// biasMode: 0 none, 1 bias[col], 2 bias[row].  outMode: 0 fp32, 1 fp16.
// ---------------------------------------------------------------------------
#define A_BYTES     32768              // 256 rows x 128B
#define B_BYTES     16384              // 128 rows x 128B
#define STAGE_BYTES (A_BYTES + B_BYTES)
#define NSTAGE      3

__global__ __launch_bounds__(512, 1)
void mma_gemm(const __half* __restrict__ A, const __half* __restrict__ B,
              const float* __restrict__ bias, int biasMode, float scale,
              float* __restrict__ Cf, __half* __restrict__ Ch,
              int outMode, int K, int ldc,
              size_t szA, size_t szB, size_t szC)
{
    extern __shared__ char smem[];
    const uint32_t sb = smem_u32(smem);
    const int tid = threadIdx.x, lane = tid & 31, wid = tid >> 5;
    const int wm = wid & 3, wn = wid >> 2;

    A += (size_t)blockIdx.z * szA;
    B += (size_t)blockIdx.z * szB;
    if (outMode == 0) Cf += (size_t)blockIdx.z * szC;
    else              Ch += (size_t)blockIdx.z * szC;

    const int rowBase = blockIdx.y * 256;
    const int colBase = blockIdx.x * 128;

    const __half* tA = A + (size_t)rowBase * K;
    const __half* tB = B + (size_t)colBase * K;

    const int NK = K >> 6;

    auto load_A = [&](uint32_t dst, const __half* g) {
        #pragma unroll
        for (int i = 0; i < 4; i++) {
            int idx = i * 512 + tid;
            int row = idx >> 3;
            int kb  = idx & 7;
            uint32_t off = row * 128 + kb * 16;
            uint32_t sw  = off ^ ((off >> 3) & 0x70);
            const void* src = (const void*)(g + (size_t)row * K + kb * 8);
            asm volatile("cp.async.cg.shared.global [%0], [%1], 16;"
                         :: "r"(dst + sw), "l"(src));
        }
    };
    auto load_B = [&](uint32_t dst, const __half* g) {
        #pragma unroll
        for (int i = 0; i < 2; i++) {
            int idx = i * 512 + tid;
            int row = idx >> 3;
            int kb  = idx & 7;
            uint32_t off = row * 128 + kb * 16;
            uint32_t sw  = off ^ ((off >> 3) & 0x70);
            const void* src = (const void*)(g + (size_t)row * K + kb * 8);
            asm volatile("cp.async.cg.shared.global [%0], [%1], 16;"
                         :: "r"(dst + sw), "l"(src));
        }
    };
    auto load_stage = [&](int buf, int c) {
        uint32_t st = sb + buf * STAGE_BYTES;
        size_t ko = (size_t)c * 64;
        load_A(st, tA + ko);
        load_B(st + A_BYTES, tB + ko);
        CP_COMMIT();
    };

    float acc[4][4][4];
    #pragma unroll
    for (int i = 0; i < 4; i++)
        #pragma unroll
        for (int j = 0; j < 4; j++)
            #pragma unroll
            for (int q = 0; q < 4; q++) acc[i][j][q] = 0.0f;

    const int lm = lane & 15;
    const int lk = lane >> 4;
    int rA[4], rB[2];
    #pragma unroll
    for (int i = 0; i < 4; i++) rA[i] = wm * 64 + i * 16 + lm;
    #pragma unroll
    for (int g = 0; g < 2; g++) rB[g] = wn * 32 + g * 16 + lm;

    load_stage(0, 0);
    if (NK > 1) load_stage(1, 1);

    int buf = 0;
    for (int c = 0; c < NK; c++) {
        if (c < NK - 1) { CP_WAIT1(); } else { CP_WAIT0(); }
        __syncthreads();
        if (c + 2 < NK) {
            int nb = buf + 2; if (nb >= NSTAGE) nb -= NSTAGE;
            load_stage(nb, c + 2);
        }

        const uint32_t stage = sb + buf * STAGE_BYTES;
        #pragma unroll
        for (int ks = 0; ks < 4; ks++) {
            const int atom = ks * 2 + lk;
            uint32_t a[4][4];
            #pragma unroll
            for (int i = 0; i < 4; i++)
                ldsm_x4(a[i], stage + rA[i] * 128 + ((atom ^ (rA[i] & 7)) << 4));
            uint32_t bf[2][4];
            #pragma unroll
            for (int g = 0; g < 2; g++)
                ldsm_x4(bf[g], stage + A_BYTES + rB[g] * 128 + ((atom ^ (rB[g] & 7)) << 4));
            #pragma unroll
            for (int i = 0; i < 4; i++)
                #pragma unroll
                for (int g = 0; g < 2; g++) {
                    mma_f16(acc[i][2 * g + 0], a[i], bf[g][0], bf[g][2]);
                    mma_f16(acc[i][2 * g + 1], a[i], bf[g][1], bf[g][3]);
                }
        }
        buf++; if (buf >= NSTAGE) buf = 0;
    }

    #pragma unroll
    for (int i = 0; i < 4; i++) {
        #pragma unroll
        for (int half = 0; half < 2; half++) {
            const int row = rowBase + wm * 64 + i * 16 + (lane >> 2) + half * 8;
            const float rb = (biasMode == 2) ? bias[row] : 0.0f;
            #pragma unroll
            for (int j = 0; j < 4; j++) {
                const int col = colBase + wn * 32 + j * 8 + (lane & 3) * 2;
                float v0 = acc[i][j][half * 2 + 0] * scale;
                float v1 = acc[i][j][half * 2 + 1] * scale;
                if (biasMode == 1) { v0 += bias[col]; v1 += bias[col + 1]; }
                else               { v0 += rb;        v1 += rb; }
                const size_t base = (size_t)row * ldc + col;
                if (outMode == 0) {
                    float2 o; o.x = v0; o.y = v1;
                    *(float2*)(Cf + base) = o;
                } else {
                    __half2 hh; hh.x = __float2half_rn(v0); hh.y = __float2half_rn(v1);
                    *(__half2*)(Ch + base) = hh;
                }
            }
        }
    }
}

// ---------------------------------------------------------------------------
// Dedicated scores GEMM: P[b] = (Q[b] @ K[b]^T) / 32, fp32 out.
// Tile 128x128 (1024 tiles -> ~1% wave tail at occ 1), BK=64, 256 threads,
// warp grid 4(m)x2(n), warp tile 32x64. 4-stage cp.async pipeline
// (128 KB smem forces occupancy 1, which the wave math requires).
// ---------------------------------------------------------------------------
#define S_TILE   16384                 // 128 rows x 128B
#define S_STAGE  (2 * S_TILE)          // 32 KB
#define S_NSTAGE 4

__global__ __launch_bounds__(256, 1)
void scores_gemm(const __half* __restrict__ Q, const __half* __restrict__ Km,
                 float* __restrict__ P)
{
    extern __shared__ char smem[];
    const uint32_t sb = smem_u32(smem);
    const int tid = threadIdx.x, lane = tid & 31, wid = tid >> 5;
    const int wm = wid & 3, wn = wid >> 2;   // 4 x 2, warp tile 32x64

    Q  += (size_t)blockIdx.z * SN * HN;
    Km += (size_t)blockIdx.z * SN * HN;
    P  += (size_t)blockIdx.z * SN * SN;

    const int rowBase = blockIdx.y * 128;
    const int colBase = blockIdx.x * 128;

    const __half* tA = Q  + (size_t)rowBase * HN;
    const __half* tB = Km + (size_t)colBase * HN;

    const int NK = HN >> 6;   // 16

    auto load_tile = [&](uint32_t dst, const __half* g) {
        #pragma unroll
        for (int i = 0; i < 4; i++) {
            int idx = i * 256 + tid;
            int row = idx >> 3;
            int kb  = idx & 7;
            uint32_t off = row * 128 + kb * 16;
            uint32_t sw  = off ^ ((off >> 3) & 0x70);
            const void* src = (const void*)(g + (size_t)row * HN + kb * 8);
            asm volatile("cp.async.cg.shared.global [%0], [%1], 16;"
                         :: "r"(dst + sw), "l"(src));
        }
    };
    auto load_stage = [&](int buf, int c) {
        uint32_t st = sb + buf * S_STAGE;
        size_t ko = (size_t)c * 64;
        load_tile(st, tA + ko);
        load_tile(st + S_TILE, tB + ko);
        CP_COMMIT();
    };

    float acc[2][8][4];
    #pragma unroll
    for (int i = 0; i < 2; i++)
        #pragma unroll
        for (int j = 0; j < 8; j++)
            #pragma unroll
            for (int q = 0; q < 4; q++) acc[i][j][q] = 0.0f;

    const int lm = lane & 15;
    const int lk = lane >> 4;
    int rA[2], rB[4];
    #pragma unroll
    for (int i = 0; i < 2; i++) rA[i] = wm * 32 + i * 16 + lm;
    #pragma unroll
    for (int g = 0; g < 4; g++) rB[g] = wn * 64 + g * 16 + lm;

    // prologue: fill 3 of 4 stages (NK=16 > 3 always)
    load_stage(0, 0);
    load_stage(1, 1);
    load_stage(2, 2);

    for (int c = 0; c < NK; c++) {
        CP_WAIT2();            // pending kept at 3 groups via empty commits
        __syncthreads();
        if (c + 3 < NK) load_stage((c + 3) & 3, c + 3);
        else            CP_COMMIT();   // empty group keeps wait_group math valid

        const uint32_t stage = sb + (c & 3) * S_STAGE;
        #pragma unroll
        for (int ks = 0; ks < 4; ks++) {
            const int atom = ks * 2 + lk;
            uint32_t a[2][4];
            #pragma unroll
            for (int i = 0; i < 2; i++)
                ldsm_x4(a[i], stage + rA[i] * 128 + ((atom ^ (rA[i] & 7)) << 4));
            uint32_t bf[4][4];
            #pragma unroll
            for (int g = 0; g < 4; g++)
                ldsm_x4(bf[g], stage + S_TILE + rB[g] * 128 + ((atom ^ (rB[g] & 7)) << 4));
            #pragma unroll
            for (int i = 0; i < 2; i++)
                #pragma unroll
                for (int g = 0; g < 4; g++) {
                    mma_f16(acc[i][2 * g + 0], a[i], bf[g][0], bf[g][2]);
                    mma_f16(acc[i][2 * g + 1], a[i], bf[g][1], bf[g][3]);
                }
        }
    }

    // epilogue: scale by 1/32, fp32 stores
    #pragma unroll
    for (int i = 0; i < 2; i++) {
        #pragma unroll
        for (int half = 0; half < 2; half++) {
            const int row = rowBase + wm * 32 + i * 16 + (lane >> 2) + half * 8;
            #pragma unroll
            for (int j = 0; j < 8; j++) {
                const int col = colBase + wn * 64 + j * 8 + (lane & 3) * 2;
                float2 o;
                o.x = acc[i][j][half * 2 + 0] * 0.03125f;
                o.y = acc[i][j][half * 2 + 1] * 0.03125f;
                *(float2*)(P + (size_t)row * SN + col) = o;
            }
        }
    }
}

// ---------------------------------------------------------------------------
// merged fp32 -> fp16 rounding for x, Wq, Wk, Wv (one launch)
// block b handles 1024 elements; x: 8192 blocks, each W: 1024 blocks
// ---------------------------------------------------------------------------
__global__ __launch_bounds__(256) void round_all(
    const float* __restrict__ x,  __half* __restrict__ xh,
    const float* __restrict__ Wq, __half* __restrict__ Wqh,
    const float* __restrict__ Wk, __half* __restrict__ Wkh,
    const float* __restrict__ Wv, __half* __restrict__ Wvh)
{
    int b = blockIdx.x;
    const float* in; __half* out; size_t off;
    if (b < 8192)       { in = x;  out = xh;  off = (size_t)b * 1024; }
    else if (b < 9216)  { in = Wq; out = Wqh; off = (size_t)(b - 8192) * 1024; }
    else if (b < 10240) { in = Wk; out = Wkh; off = (size_t)(b - 9216) * 1024; }
    else                { in = Wv; out = Wvh; off = (size_t)(b - 10240) * 1024; }
    size_t i = off + (size_t)threadIdx.x * 4;
    float4 v = *(const float4*)(in + i);
    __half2 ha; ha.x = __float2half_rn(v.x); ha.y = __float2half_rn(v.y);
    __half2 hb; hb.x = __float2half_rn(v.z); hb.y = __float2half_rn(v.w);
    *(__half2*)(out + i) = ha; *(__half2*)(out + i + 2) = hb;
}

// ---------------------------------------------------------------------------
// row softmax: fp32 in, fp16 out. One block per row of 2048.
// ---------------------------------------------------------------------------
__global__ __launch_bounds__(256) void softmax_h(
    const float* __restrict__ P, __half* __restrict__ Ph, int n)
{
    const float* row = P + (size_t)blockIdx.x * n;
    __half* oh = Ph + (size_t)blockIdx.x * n;
    const int tid = threadIdx.x, lane = tid & 31, wd = tid >> 5;
    __shared__ float red[8];

    float v[8]; float m = -INFINITY;
    #pragma unroll
    for (int i = 0; i < 8; i++) { v[i] = row[tid + i * 256]; m = fmaxf(m, v[i]); }
    #pragma unroll
    for (int o = 16; o > 0; o >>= 1) m = fmaxf(m, __shfl_xor_sync(~0u, m, o));
    if (lane == 0) red[wd] = m;
    __syncthreads();
    float mb = red[0];
    #pragma unroll
    for (int w = 1; w < 8; w++) mb = fmaxf(mb, red[w]);
    __syncthreads();

    float s = 0.0f;
    #pragma unroll
    for (int i = 0; i < 8; i++) { v[i] = __expf(v[i] - mb); s += v[i]; }
    #pragma unroll
    for (int o = 16; o > 0; o >>= 1) s += __shfl_xor_sync(~0u, s, o);
    if (lane == 0) red[wd] = s;
    __syncthreads();
    float sb = 0.0f;
    #pragma unroll
    for (int w = 0; w < 8; w++) sb += red[w];
    const float r = 1.0f / sb;

    #pragma unroll
    for (int i = 0; i < 8; i++)
        oh[tid + i * 256] = __float2half_rn(v[i] * r);
}

// ---------------------------------------------------------------------------
extern "C" void kernel_launch(void* const* d_in, const int* in_sizes, int n_in,
                              void* d_out, int out_size)
{
    (void)in_sizes; (void)n_in; (void)out_size;
    const float* x  = (const float*)d_in[0];
    const float* Wq = (const float*)d_in[1];
    const float* bq = (const float*)d_in[2];
    const float* Wk = (const float*)d_in[3];
    const float* bk = (const float*)d_in[4];
    const float* Wv = (const float*)d_in[5];
    const float* bv = (const float*)d_in[6];
    float* out = (float*)d_out;

    const int smem  = NSTAGE * STAGE_BYTES;      // 144 KB
    const int smemS = S_NSTAGE * S_STAGE;        // 128 KB
    cudaFuncSetAttribute(mma_gemm, cudaFuncAttributeMaxDynamicSharedMemorySize, smem);
    cudaFuncSetAttribute(scores_gemm, cudaFuncAttributeMaxDynamicSharedMemorySize, smemS);

    __half *xh, *Wqh, *Wkh, *Wvh, *Qh, *Kh, *Vth, *Ph;
    float *P;
    cudaGetSymbolAddress((void**)&xh, g_xh);
    cudaGetSymbolAddress((void**)&Wqh, g_Wqh);
    cudaGetSymbolAddress((void**)&Wkh, g_Wkh);
    cudaGetSymbolAddress((void**)&Wvh, g_Wvh);
    cudaGetSymbolAddress((void**)&Qh, g_Qh);
    cudaGetSymbolAddress((void**)&Kh, g_KhA);
    cudaGetSymbolAddress((void**)&Vth, g_Vth);
    cudaGetSymbolAddress((void**)&P, g_P);
    cudaGetSymbolAddress((void**)&Ph, g_Ph);

    // 0) round all fp32 inputs to fp16 in one launch
    round_all<<<11264, 256>>>(x, xh, Wq, Wqh, Wk, Wkh, Wv, Wvh);

    // 1) Q = xh @ Wqh^T + bq -> Qh;  K = xh @ Wkh^T + bk -> Kh
    {
        dim3 g(HN / 128, MTOT / 256, 1);
        mma_gemm<<<g, 512, smem>>>(xh, Wqh, bq, 1, 1.0f,
                                   nullptr, Qh, 1, HN, HN, 0, 0, 0);
        mma_gemm<<<g, 512, smem>>>(xh, Wkh, bk, 1, 1.0f,
                                   nullptr, Kh, 1, HN, HN, 0, 0, 0);
    }
    // 2) Vt_b = Wvh @ xh_b^T + bv[row] -> Vth
    {
        dim3 g(SN / 128, HN / 256, BN);
        mma_gemm<<<g, 512, smem>>>(Wvh, xh, bv, 2, 1.0f,
                                   nullptr, Vth, 1, HN, SN,
                                   0, (size_t)SN * HN, (size_t)HN * SN);
    }
    // 3) scores = Qh_b @ Kh_b^T / 32 -> fp32 P  (128x128 tiles, 1024 CTAs)
    {
        dim3 g(SN / 128, SN / 128, BN);
        scores_gemm<<<g, 256, smemS>>>(Qh, Kh, P);
    }
    // 4) softmax rows -> Ph
    softmax_h<<<BN * SN, 256>>>(P, Ph, SN);

    // 5) out = Ph_b @ Vth_b^T -> fp32
    {
        dim3 g(HN / 128, SN / 256, BN);
        mma_gemm<<<g, 512, smem>>>(Ph, Vth, nullptr, 0, 1.0f,
                                   out, nullptr, 0, SN, HN,
                                   (size_t)SN * SN, (size_t)HN * SN, (size_t)SN * HN);
    }
}